// round 13
// baseline (speedup 1.0000x reference)
#include <cuda_runtime.h>
#include <cuda_fp16.h>
#include <math.h>
#include <stdint.h>

#define NN 8192
#define FIN 512
#define FH 256
#define FOUT 64
#define LRELU_A 0.2f

// ---------------- scratch (no allocations allowed) ----------------
__device__ float g_h1[NN * FH];
__device__ float g_y1[NN * FH];
__device__ float g_h2[NN * FOUT];
__device__ __half g_h1T[FH * NN];
__device__ __half g_h2T[FOUT * NN];
__device__ float g_s1[NN], g_t1[NN];
__device__ float g_s2[NN], g_t2[NN];
__device__ int g_tmaxi[2];
__device__ uint32_t g_adjbits[(size_t)NN * (NN / 32)];
__device__ __align__(16) float g_E12[2 * NN];          // (exp(t), exp(0.2t)) per j
__device__ float g_pacc[2 * (size_t)NN * FH];          // split-j partial acc (reused)
__device__ float g_pl[2 * NN];                         // split-j partial l

__device__ __forceinline__ float elu1(float x) { return x > 0.f ? x : expm1f(x); }

__device__ __forceinline__ int enc_f(float f) {
    int i = __float_as_int(f);
    return i < 0 ? (i ^ 0x7fffffff) : i;
}
__device__ __forceinline__ float dec_f(int i) {
    return __int_as_float(i < 0 ? (i ^ 0x7fffffff) : i);
}

__device__ __forceinline__ void ldsm4(uint32_t& r0, uint32_t& r1, uint32_t& r2,
                                      uint32_t& r3, uint32_t addr) {
    asm volatile("ldmatrix.sync.aligned.m8n8.x4.shared.b16 {%0,%1,%2,%3}, [%4];"
                 : "=r"(r0), "=r"(r1), "=r"(r2), "=r"(r3) : "r"(addr));
}

__device__ __forceinline__ void mma16816(float d[4], uint32_t a0, uint32_t a1,
                                         uint32_t a2, uint32_t a3,
                                         uint32_t b0, uint32_t b1) {
    asm volatile(
        "mma.sync.aligned.m16n8k16.row.col.f32.f16.f16.f32 "
        "{%0,%1,%2,%3}, {%4,%5,%6,%7}, {%8,%9}, {%0,%1,%2,%3};"
        : "+f"(d[0]), "+f"(d[1]), "+f"(d[2]), "+f"(d[3])
        : "r"(a0), "r"(a1), "r"(a2), "r"(a3), "r"(b0), "r"(b1));
}

__device__ __forceinline__ void cp16(uint32_t dst, const void* src) {
    asm volatile("cp.async.cg.shared.global [%0], [%1], 16;" :: "r"(dst), "l"(src));
}

// =================================================================
// GEMM: C[M,N] = A[M,K] @ W[N,K]^T + bias[N]. Also re-inits tmax ints.
// =================================================================
__global__ __launch_bounds__(256) void gemm_bias(
    const float* __restrict__ A, const float* __restrict__ W,
    const float* __restrict__ bias, float* __restrict__ C,
    int M, int N, int K)
{
    const int BM = 128, BN = 64, BK = 16;
    __shared__ float As[BK][BM + 1];
    __shared__ float Bs[BK][BN + 1];

    int tid = threadIdx.x;
    int bx = blockIdx.x, by = blockIdx.y;
    if (bx == 0 && by == 0 && tid == 0) {
        g_tmaxi[0] = (int)0x80000000;
        g_tmaxi[1] = (int)0x80000000;
    }
    int ty = tid >> 4, tx = tid & 15;
    int ar = tid >> 2, ac4 = (tid & 3) * 4;

    float acc[8][4];
#pragma unroll
    for (int i = 0; i < 8; i++)
#pragma unroll
        for (int j = 0; j < 4; j++) acc[i][j] = 0.f;

    for (int k0 = 0; k0 < K; k0 += BK) {
        float4 a0 = *(const float4*)(A + (size_t)(by * BM + ar) * K + k0 + ac4);
        float4 a1 = *(const float4*)(A + (size_t)(by * BM + ar + 64) * K + k0 + ac4);
        float4 b0 = *(const float4*)(W + (size_t)(bx * BN + ar) * K + k0 + ac4);
        __syncthreads();
        As[ac4 + 0][ar] = a0.x; As[ac4 + 1][ar] = a0.y;
        As[ac4 + 2][ar] = a0.z; As[ac4 + 3][ar] = a0.w;
        As[ac4 + 0][ar + 64] = a1.x; As[ac4 + 1][ar + 64] = a1.y;
        As[ac4 + 2][ar + 64] = a1.z; As[ac4 + 3][ar + 64] = a1.w;
        Bs[ac4 + 0][ar] = b0.x; Bs[ac4 + 1][ar] = b0.y;
        Bs[ac4 + 2][ar] = b0.z; Bs[ac4 + 3][ar] = b0.w;
        __syncthreads();
#pragma unroll
        for (int k = 0; k < BK; k++) {
            float ra[8], rb[4];
#pragma unroll
            for (int i = 0; i < 8; i++) ra[i] = As[k][ty * 8 + i];
#pragma unroll
            for (int j = 0; j < 4; j++) rb[j] = Bs[k][tx * 4 + j];
#pragma unroll
            for (int i = 0; i < 8; i++)
#pragma unroll
                for (int j = 0; j < 4; j++) acc[i][j] = fmaf(ra[i], rb[j], acc[i][j]);
        }
    }

    float4 bv = ((const float4*)bias)[bx * 16 + tx];
#pragma unroll
    for (int i = 0; i < 8; i++) {
        int row = by * BM + ty * 8 + i;
        float4 v;
        v.x = acc[i][0] + bv.x; v.y = acc[i][1] + bv.y;
        v.z = acc[i][2] + bv.z; v.w = acc[i][3] + bv.w;
        ((float4*)(C + (size_t)row * N))[bx * 16 + tx] = v;
    }
}

// =================================================================
// transpose + fp16 convert (z==0); adjacency bit-pack (z==1)
// =================================================================
__global__ __launch_bounds__(256) void transpose_pack(
    const float* __restrict__ h, __half* __restrict__ hT, int F,
    const int* __restrict__ adj, uint32_t* __restrict__ bits)
{
    if (blockIdx.z == 1) {
        int bid = blockIdx.x + blockIdx.y * gridDim.x;
        int wd = threadIdx.x;
#pragma unroll
        for (int r = 0; r < 4; r++) {
            int row = bid * 4 + r;
            const int4* src = (const int4*)(adj + (size_t)row * NN + wd * 32);
            uint32_t m = 0;
#pragma unroll
            for (int q = 0; q < 8; q++) {
                int4 v = src[q];
                m |= (v.x != 0 ? 1u : 0u) << (q * 4 + 0);
                m |= (v.y != 0 ? 1u : 0u) << (q * 4 + 1);
                m |= (v.z != 0 ? 1u : 0u) << (q * 4 + 2);
                m |= (v.w != 0 ? 1u : 0u) << (q * 4 + 3);
            }
            bits[(size_t)row * (NN / 32) + wd] = m;
        }
        return;
    }

    __shared__ float ts[32][33];
    int n0 = blockIdx.x * 32, c0 = blockIdx.y * 32;
    int r = threadIdx.x >> 3, cc = (threadIdx.x & 7) * 4;

    float4 v = *(const float4*)(h + (size_t)(n0 + r) * F + c0 + cc);
    ts[r][cc + 0] = v.x; ts[r][cc + 1] = v.y;
    ts[r][cc + 2] = v.z; ts[r][cc + 3] = v.w;
    __syncthreads();

    int c = threadIdx.x >> 3, nn2 = (threadIdx.x & 7) * 4;
    __half2 p0 = __floats2half2_rn(ts[nn2 + 0][c], ts[nn2 + 1][c]);
    __half2 p1 = __floats2half2_rn(ts[nn2 + 2][c], ts[nn2 + 3][c]);
    union { __half2 h2[2]; uint2 u; } cv;
    cv.h2[0] = p0; cv.h2[1] = p1;
    *(uint2*)(hT + (size_t)(c0 + c) * NN + n0 + nn2) = cv.u;
}

// =================================================================
// s/t projections + E12 table + block-reduced atomicMax of t
// =================================================================
template <int F>
__global__ __launch_bounds__(256) void st_kernel(
    const float* __restrict__ h, const float* __restrict__ a,
    float* __restrict__ s, float* __restrict__ t,
    float* __restrict__ E12, int* __restrict__ tmax)
{
    __shared__ float wmax[8];
    int warp = threadIdx.x >> 5, lane = threadIdx.x & 31;
    int row = blockIdx.x * 8 + warp;
    const float* hr = h + (size_t)row * F;
    float lo = 0.f, hi = 0.f;
#pragma unroll
    for (int f = lane; f < F; f += 32) {
        float v = hr[f];
        lo = fmaf(v, a[f], lo);
        hi = fmaf(v, a[F + f], hi);
    }
#pragma unroll
    for (int o = 16; o; o >>= 1) {
        lo += __shfl_xor_sync(0xffffffffu, lo, o);
        hi += __shfl_xor_sync(0xffffffffu, hi, o);
    }
    if (lane == 0) {
        s[row] = lo; t[row] = hi;
        E12[2 * row] = __expf(hi);
        E12[2 * row + 1] = __expf(LRELU_A * hi);
        wmax[warp] = hi;
    }
    __syncthreads();
    if (threadIdx.x == 0) {
        float m = wmax[0];
#pragma unroll
        for (int q = 1; q < 8; q++) m = fmaxf(m, wmax[q]);
        atomicMax(tmax, enc_f(m));
    }
}

// =================================================================
// Fused GAT attention (partial): fp16 mma.sync + cp.async + ldmatrix.
// BM rows x NFB cols per CTA, NTH threads, TPI 64-j subtiles/iter,
// SPLITJ-way j-split, CH row-chunks per warp (B-fragment reuse).
// Writes RAW partial acc + l to scratch.
// =================================================================
template <int NF, int NFB, int BM, int NTH, int TPI, int SPLITJ, int CH, int MINB>
__global__ __launch_bounds__(NTH, MINB) void attn_mma(
    const __half* __restrict__ hTg, const uint32_t* __restrict__ bits,
    const float* __restrict__ sG, const float* __restrict__ abG,
    const int* __restrict__ tmaxI, const float* __restrict__ E12g,
    float* __restrict__ paccG, float* __restrict__ plG)
{
    constexpr int NW = NTH / 32;
    constexpr int WRB = BM / (16 * CH);         // row-group warps
    constexpr int WC = NW / WRB;                // col-group warps
    constexpr int PERCOL = NFB / WC;
    constexpr int NCT = PERCOL / 8;
    constexpr int NQ = NCT / 2;
    constexpr int THT = NFB * 128;
    constexpr int TPS = BM * 128;
    constexpr int HTB = TPI * THT;
    constexpr int PSB = TPI * TPS;
    constexpr int PERT = NFB * 8 / NTH;
    constexpr int NIT = NN / (64 * TPI * SPLITJ);
    constexpr int NBLK = NF / NFB;
    constexpr int ROWDIV = NBLK * SPLITJ;
    constexpr int TPR = NTH / BM;               // phase-A threads per row
    constexpr int JPT = 64 / TPR;               // j per thread per subtile
    constexpr int NST = (JPT * 2) / 16;         // uint4 Ps stores per subtile

    extern __shared__ char smem[];
    const uint32_t sb = (uint32_t)__cvta_generic_to_shared(smem);

    const int tid = threadIdx.x;
    const int lane = tid & 31, w = tid >> 5;
    const int g = lane >> 2, tig = lane & 3;
    const int wr = w / WC, wc = w % WC;
    const int C0 = wc * PERCOL;
    const int bid = blockIdx.x;
    const int rb = bid / ROWDIV;
    const int r2 = bid % ROWDIV;
    const int cb = r2 / SPLITJ;
    const int jh = r2 % SPLITJ;
    const int i0 = rb * BM, c0 = cb * NFB;
    const int jbase = jh * (NN / SPLITJ);

    // phase-A mapping: TPR threads per row, JPT j per thread per subtile
    const int ar = tid / TPR, acg = tid % TPR;
    const float svp = sG[i0 + ar] + abG[0];
    const float Ma = svp + dec_f(tmaxI[0]);
    const float M = fmaxf(Ma, LRELU_A * Ma);
    const float c1 = __expf(svp - M);
    const float c2 = __expf(LRELU_A * svp - M);
    const float c3 = __expf(-svp);
    float lacc = 0.f;

    float acc[CH][NCT][4];
#pragma unroll
    for (int c = 0; c < CH; c++)
#pragma unroll
        for (int ct = 0; ct < NCT; ct++)
#pragma unroll
            for (int q = 0; q < 4; q++) acc[c][ct][q] = 0.f;

    const uint32_t* brow = bits + (size_t)(i0 + ar) * (NN / 32);
    const uint32_t xr = (uint32_t)((ar & 7) << 4);
    const uint32_t xO = (uint32_t)((lane & 7) << 4);
    const uint32_t aBoff = (uint32_t)((lane >> 4) << 4);
    const int bColB = (lane & 7) + ((lane >> 4) << 3);
    const uint32_t bBoff = (uint32_t)(((lane >> 3) & 1) << 4);

    uint32_t aOffA[4], bOffA[4];
#pragma unroll
    for (int k = 0; k < 4; k++) {
        aOffA[k] = (((uint32_t)(32 * k)) + aBoff) ^ xO;
        bOffA[k] = (((uint32_t)(32 * k)) + bBoff) ^ xO;
    }
    const uint32_t cBase = (uint32_t)(C0 + bColB) * 128;
    uint32_t aRowB[CH];
#pragma unroll
    for (int c = 0; c < CH; c++)
        aRowB[c] = (uint32_t)(wr * 16 + c * (WRB * 16) + (lane & 7) +
                              ((lane >> 3) & 1) * 8) * 128;

    uint32_t bwv[TPI];

#define ISSUE_CP(J0, BUF) do {                                                 \
    uint32_t hb = sb + (BUF) * HTB;                                            \
    _Pragma("unroll")                                                          \
    for (int tp = 0; tp < TPI; tp++) {                                         \
        _Pragma("unroll")                                                      \
        for (int u = 0; u < PERT; u++) {                                       \
            int ci = tid * PERT + u;                                           \
            int rr = ci >> 3, ch2 = ci & 7;                                    \
            uint32_t dst = hb + tp * THT + rr * 128 +                          \
                           (((uint32_t)(ch2 * 16)) ^ (((uint32_t)(rr & 7)) << 4)); \
            cp16(dst, hTg + (size_t)(c0 + rr) * NN + (J0) + tp * 64 + ch2 * 8); \
        }                                                                      \
    }                                                                          \
    asm volatile("cp.async.commit_group;" ::: "memory");                       \
} while (0)

#define LOAD_BITS(J0) do {                                                     \
    _Pragma("unroll")                                                          \
    for (int tp = 0; tp < TPI; tp++)                                           \
        bwv[tp] = brow[(((J0) + tp * 64) >> 5) + ((acg * JPT) >> 5)];          \
} while (0)

#define PHASE_A(BUF, J0) do {                                                  \
    _Pragma("unroll")                                                          \
    for (int tp = 0; tp < TPI; tp++) {                                         \
        const float4* ep = (const float4*)(E12g + 2 * ((J0) + tp * 64 + acg * JPT)); \
        uint32_t mb = bwv[tp] >> ((acg * JPT) & 31);                           \
        union { __half2 h2[JPT / 2]; uint4 u[NST]; } cvv;                      \
        _Pragma("unroll")                                                      \
        for (int q = 0; q < JPT / 2; q++) {                                    \
            float4 v = ep[q];                                                  \
            float p0 = (v.x >= c3) ? c1 * v.x : c2 * v.y;                      \
            p0 = ((mb >> (2 * q)) & 1u) ? p0 : 0.f;                            \
            float p1 = (v.z >= c3) ? c1 * v.z : c2 * v.w;                      \
            p1 = ((mb >> (2 * q + 1)) & 1u) ? p1 : 0.f;                        \
            lacc += p0 + p1;                                                   \
            cvv.h2[q] = __floats2half2_rn(p0, p1);                             \
        }                                                                      \
        char* pbase = smem + 2 * HTB + (BUF) * PSB + tp * TPS + ar * 128;      \
        _Pragma("unroll")                                                      \
        for (int w2 = 0; w2 < NST; w2++)                                       \
            *(uint4*)(pbase + (((uint32_t)(acg * (JPT * 2) + w2 * 16)) ^ xr)) = cvv.u[w2]; \
    }                                                                          \
} while (0)

    // ---- prologue ----
    ISSUE_CP(jbase, 0);
    LOAD_BITS(jbase);
    PHASE_A(0, jbase);

    for (int i = 0; i < NIT; i++) {
        asm volatile("cp.async.wait_group 0;" ::: "memory");
        __syncthreads();

        const int cbf = i & 1, nb = (i + 1) & 1;
        const int jn = jbase + (i + 1) * 64 * TPI;
        if (i + 1 < NIT) {
            ISSUE_CP(jn, nb);
            LOAD_BITS(jn);
        }

        // ---- mma(i): B fragments shared across CH row-chunks ----
        const uint32_t psA0 = sb + 2 * HTB + (uint32_t)cbf * PSB;
        const uint32_t htA0 = sb + (uint32_t)cbf * HTB + cBase;
#pragma unroll
        for (int tp = 0; tp < TPI; tp++) {
            const uint32_t psA = psA0 + tp * TPS;
            const uint32_t htA = htA0 + tp * THT;
#pragma unroll
            for (int k = 0; k < 4; k++) {
                uint32_t A[CH][4];
#pragma unroll
                for (int c = 0; c < CH; c++)
                    ldsm4(A[c][0], A[c][1], A[c][2], A[c][3],
                          psA + aRowB[c] + aOffA[k]);
#pragma unroll
                for (int q = 0; q < NQ; q++) {
                    uint32_t b0, b1, b2, b3;
                    ldsm4(b0, b1, b2, b3, htA + (uint32_t)(q * 2048) + bOffA[k]);
#pragma unroll
                    for (int c = 0; c < CH; c++) {
                        mma16816(acc[c][2 * q + 0], A[c][0], A[c][1], A[c][2],
                                 A[c][3], b0, b1);
                        mma16816(acc[c][2 * q + 1], A[c][0], A[c][1], A[c][2],
                                 A[c][3], b2, b3);
                    }
                }
            }
        }

        if (i + 1 < NIT) PHASE_A(nb, jn);
    }

    // ---- partial l (once per row; cb==0 only) ----
#pragma unroll
    for (int o = 1; o < TPR; o <<= 1)
        lacc += __shfl_xor_sync(0xffffffffu, lacc, o);
    if (acg == 0 && cb == 0) plG[jh * NN + i0 + ar] = lacc;

    // ---- raw partial acc ----
    float* pj = paccG + (size_t)jh * NN * NF;
#pragma unroll
    for (int c = 0; c < CH; c++) {
        const int r0 = i0 + wr * 16 + c * (WRB * 16) + g;
        const int r1 = r0 + 8;
#pragma unroll
        for (int ct = 0; ct < NCT; ct++) {
            int cc = c0 + C0 + 8 * ct + 2 * tig;
            *(float2*)(pj + (size_t)r0 * NF + cc) =
                make_float2(acc[c][ct][0], acc[c][ct][1]);
            *(float2*)(pj + (size_t)r1 * NF + cc) =
                make_float2(acc[c][ct][2], acc[c][ct][3]);
        }
    }
#undef ISSUE_CP
#undef LOAD_BITS
#undef PHASE_A
}

// =================================================================
// combine (mid layer): y = elu(elu((p0+p1)/(l0+l1))), elementwise
// =================================================================
__global__ __launch_bounds__(256) void comb_mid(
    const float* __restrict__ pacc, const float* __restrict__ pl,
    float* __restrict__ y)
{
    int idx = blockIdx.x * 256 + threadIdx.x;       // float4 index
    int row = idx / (FH / 4);
    float inv = 1.f / (pl[row] + pl[NN + row]);
    float4 a = ((const float4*)pacc)[idx];
    float4 b = ((const float4*)pacc)[idx + NN * (FH / 4)];
    float4 o;
    o.x = elu1(elu1((a.x + b.x) * inv));
    o.y = elu1(elu1((a.y + b.y) * inv));
    o.z = elu1(elu1((a.z + b.z) * inv));
    o.w = elu1(elu1((a.w + b.w) * inv));
    ((float4*)y)[idx] = o;
}

// =================================================================
// combine (final): out = log_softmax(elu((p0+p1)/(l0+l1))), per row
// =================================================================
__global__ __launch_bounds__(256) void comb_fin(
    const float* __restrict__ pacc, const float* __restrict__ pl,
    float* __restrict__ out)
{
    int tid = threadIdx.x;
    int qr = tid >> 3, ql = tid & 7;
    int row = blockIdx.x * 32 + qr;
    float inv = 1.f / (pl[row] + pl[NN + row]);
    const float* a0 = pacc + (size_t)row * FOUT + ql * 8;
    const float* a1 = a0 + (size_t)NN * FOUT;
    float z[8];
    {
        float4 u0 = ((const float4*)a0)[0], u1 = ((const float4*)a0)[1];
        float4 v0 = ((const float4*)a1)[0], v1 = ((const float4*)a1)[1];
        z[0] = elu1((u0.x + v0.x) * inv); z[1] = elu1((u0.y + v0.y) * inv);
        z[2] = elu1((u0.z + v0.z) * inv); z[3] = elu1((u0.w + v0.w) * inv);
        z[4] = elu1((u1.x + v1.x) * inv); z[5] = elu1((u1.y + v1.y) * inv);
        z[6] = elu1((u1.z + v1.z) * inv); z[7] = elu1((u1.w + v1.w) * inv);
    }
    float mx = z[0];
#pragma unroll
    for (int i = 1; i < 8; i++) mx = fmaxf(mx, z[i]);
    mx = fmaxf(mx, __shfl_xor_sync(0xffffffffu, mx, 1));
    mx = fmaxf(mx, __shfl_xor_sync(0xffffffffu, mx, 2));
    mx = fmaxf(mx, __shfl_xor_sync(0xffffffffu, mx, 4));
    float se = 0.f;
#pragma unroll
    for (int i = 0; i < 8; i++) se += __expf(z[i] - mx);
    se += __shfl_xor_sync(0xffffffffu, se, 1);
    se += __shfl_xor_sync(0xffffffffu, se, 2);
    se += __shfl_xor_sync(0xffffffffu, se, 4);
    float lse = mx + logf(se);
    float4 o0 = make_float4(z[0] - lse, z[1] - lse, z[2] - lse, z[3] - lse);
    float4 o1 = make_float4(z[4] - lse, z[5] - lse, z[6] - lse, z[7] - lse);
    float* op = out + (size_t)row * FOUT + ql * 8;
    ((float4*)op)[0] = o0;
    ((float4*)op)[1] = o1;
}

// =================================================================
extern "C" void kernel_launch(void* const* d_in, const int* in_sizes, int n_in,
                              void* d_out, int out_size)
{
    const float* x   = (const float*)d_in[0];
    const int*   adj = (const int*)  d_in[1];
    const float* W1  = (const float*)d_in[2];
    const float* b1  = (const float*)d_in[3];
    const float* a1  = (const float*)d_in[4];
    const float* ab1 = (const float*)d_in[5];
    const float* W2  = (const float*)d_in[6];
    const float* b2  = (const float*)d_in[7];
    const float* a2  = (const float*)d_in[8];
    const float* ab2 = (const float*)d_in[9];
    float* out = (float*)d_out;

    void *h1p, *y1p, *h2p, *h1tp, *h2tp, *s1p, *t1p, *s2p, *t2p, *tmp, *abp,
         *e12p, *pap, *plp;
    cudaGetSymbolAddress(&h1p, g_h1);
    cudaGetSymbolAddress(&y1p, g_y1);
    cudaGetSymbolAddress(&h2p, g_h2);
    cudaGetSymbolAddress(&h1tp, g_h1T);
    cudaGetSymbolAddress(&h2tp, g_h2T);
    cudaGetSymbolAddress(&s1p, g_s1);
    cudaGetSymbolAddress(&t1p, g_t1);
    cudaGetSymbolAddress(&s2p, g_s2);
    cudaGetSymbolAddress(&t2p, g_t2);
    cudaGetSymbolAddress(&tmp, g_tmaxi);
    cudaGetSymbolAddress(&abp, g_adjbits);
    cudaGetSymbolAddress(&e12p, g_E12);
    cudaGetSymbolAddress(&pap, g_pacc);
    cudaGetSymbolAddress(&plp, g_pl);
    float* h1 = (float*)h1p; float* y1 = (float*)y1p; float* h2 = (float*)h2p;
    __half* h1T = (__half*)h1tp; __half* h2T = (__half*)h2tp;
    float* s1 = (float*)s1p; float* t1 = (float*)t1p;
    float* s2 = (float*)s2p; float* t2 = (float*)t2p;
    int* tmaxi = (int*)tmp;
    uint32_t* abits = (uint32_t*)abp;
    float* E12 = (float*)e12p;
    float* pacc = (float*)pap;
    float* pl = (float*)plp;

    // attn1: NFB=128, BM=64, 256thr, TPI=1, SPLITJ=2, CH=2, 3 CTAs/SM
    // attn2: NFB=64,  BM=32, 256thr, TPI=2, SPLITJ=2, CH=1, 4 CTAs/SM
    const int SM1 = 2 * (1 * 128 * 128) + 2 * (1 * 64 * 128);   // 49152
    const int SM2 = 2 * (2 * 64 * 128) + 2 * (2 * 32 * 128);    // 49152
    cudaFuncSetAttribute((const void*)attn_mma<FH, 128, 64, 256, 1, 2, 2, 3>,
                         cudaFuncAttributeMaxDynamicSharedMemorySize, SM1);
    cudaFuncSetAttribute((const void*)attn_mma<FOUT, 64, 32, 256, 2, 2, 1, 4>,
                         cudaFuncAttributeMaxDynamicSharedMemorySize, SM2);

    // Layer 1  (attn_mma is the 4th launch -> gets profiled by ncu)
    gemm_bias<<<dim3(FH / 64, NN / 128), 256>>>(x, W1, b1, h1, NN, FH, FIN);
    transpose_pack<<<dim3(NN / 32, FH / 32, 2), 256>>>(h1, h1T, FH, adj, abits);
    st_kernel<FH><<<NN / 8, 256>>>(h1, a1, s1, t1, E12, tmaxi);
    attn_mma<FH, 128, 64, 256, 1, 2, 2, 3><<<(NN / 64) * 4, 256, SM1>>>(
        h1T, abits, s1, ab1, tmaxi, E12, pacc, pl);
    comb_mid<<<NN * FH / 4 / 256, 256>>>(pacc, pl, y1);

    // Layer 2
    gemm_bias<<<dim3(FOUT / 64, NN / 128), 256>>>(y1, W2, b2, h2, NN, FOUT, FH);
    transpose_pack<<<dim3(NN / 32, FOUT / 32, 1), 256>>>(h2, h2T, FOUT, adj, abits);
    st_kernel<FOUT><<<NN / 8, 256>>>(h2, a2, s2, t2, E12, tmaxi + 1);
    attn_mma<FOUT, 64, 32, 256, 2, 2, 1, 4><<<(NN / 32) * 2, 256, SM2>>>(
        h2T, abits, s2, ab2, tmaxi + 1, E12, pacc, pl);
    comb_fin<<<NN / 32, 256>>>(pacc, pl, out);
}

// round 14
// speedup vs baseline: 1.1160x; 1.1160x over previous
#include <cuda_runtime.h>
#include <cuda_fp16.h>
#include <math.h>
#include <stdint.h>

#define NN 8192
#define FIN 512
#define FH 256
#define FOUT 64
#define LRELU_A 0.2f

// ---------------- scratch (no allocations allowed) ----------------
__device__ float g_h1[NN * FH];
__device__ float g_y1[NN * FH];
__device__ float g_h2[NN * FOUT];
__device__ __half g_h1T[FH * NN];
__device__ __half g_h2T[FOUT * NN];
__device__ float g_s1[NN], g_t1[NN];
__device__ float g_s2[NN], g_t2[NN];
__device__ int g_tmaxi[2];
__device__ uint32_t g_adjbits[(size_t)NN * (NN / 32)];
__device__ __align__(16) float g_E12[2 * NN];          // (exp(t), exp(0.2t)) per j
__device__ float g_pacc[2 * (size_t)NN * FH];          // split-j partial acc (reused)
__device__ float g_pl[2 * NN];                         // split-j partial l

__device__ __forceinline__ float elu1(float x) { return x > 0.f ? x : expm1f(x); }

__device__ __forceinline__ int enc_f(float f) {
    int i = __float_as_int(f);
    return i < 0 ? (i ^ 0x7fffffff) : i;
}
__device__ __forceinline__ float dec_f(int i) {
    return __int_as_float(i < 0 ? (i ^ 0x7fffffff) : i);
}

__device__ __forceinline__ void ldsm4(uint32_t& r0, uint32_t& r1, uint32_t& r2,
                                      uint32_t& r3, uint32_t addr) {
    asm volatile("ldmatrix.sync.aligned.m8n8.x4.shared.b16 {%0,%1,%2,%3}, [%4];"
                 : "=r"(r0), "=r"(r1), "=r"(r2), "=r"(r3) : "r"(addr));
}

__device__ __forceinline__ void mma16816(float d[4], uint32_t a0, uint32_t a1,
                                         uint32_t a2, uint32_t a3,
                                         uint32_t b0, uint32_t b1) {
    asm volatile(
        "mma.sync.aligned.m16n8k16.row.col.f32.f16.f16.f32 "
        "{%0,%1,%2,%3}, {%4,%5,%6,%7}, {%8,%9}, {%0,%1,%2,%3};"
        : "+f"(d[0]), "+f"(d[1]), "+f"(d[2]), "+f"(d[3])
        : "r"(a0), "r"(a1), "r"(a2), "r"(a3), "r"(b0), "r"(b1));
}

__device__ __forceinline__ void cp16(uint32_t dst, const void* src) {
    asm volatile("cp.async.cg.shared.global [%0], [%1], 16;" :: "r"(dst), "l"(src));
}

// =================================================================
// GEMM: C[M,N] = A[M,K] @ W[N,K]^T + bias[N]. Also re-inits tmax ints.
// =================================================================
__global__ __launch_bounds__(256) void gemm_bias(
    const float* __restrict__ A, const float* __restrict__ W,
    const float* __restrict__ bias, float* __restrict__ C,
    int M, int N, int K)
{
    const int BM = 128, BN = 64, BK = 16;
    __shared__ float As[BK][BM + 1];
    __shared__ float Bs[BK][BN + 1];

    int tid = threadIdx.x;
    int bx = blockIdx.x, by = blockIdx.y;
    if (bx == 0 && by == 0 && tid == 0) {
        g_tmaxi[0] = (int)0x80000000;
        g_tmaxi[1] = (int)0x80000000;
    }
    int ty = tid >> 4, tx = tid & 15;
    int ar = tid >> 2, ac4 = (tid & 3) * 4;

    float acc[8][4];
#pragma unroll
    for (int i = 0; i < 8; i++)
#pragma unroll
        for (int j = 0; j < 4; j++) acc[i][j] = 0.f;

    for (int k0 = 0; k0 < K; k0 += BK) {
        float4 a0 = *(const float4*)(A + (size_t)(by * BM + ar) * K + k0 + ac4);
        float4 a1 = *(const float4*)(A + (size_t)(by * BM + ar + 64) * K + k0 + ac4);
        float4 b0 = *(const float4*)(W + (size_t)(bx * BN + ar) * K + k0 + ac4);
        __syncthreads();
        As[ac4 + 0][ar] = a0.x; As[ac4 + 1][ar] = a0.y;
        As[ac4 + 2][ar] = a0.z; As[ac4 + 3][ar] = a0.w;
        As[ac4 + 0][ar + 64] = a1.x; As[ac4 + 1][ar + 64] = a1.y;
        As[ac4 + 2][ar + 64] = a1.z; As[ac4 + 3][ar + 64] = a1.w;
        Bs[ac4 + 0][ar] = b0.x; Bs[ac4 + 1][ar] = b0.y;
        Bs[ac4 + 2][ar] = b0.z; Bs[ac4 + 3][ar] = b0.w;
        __syncthreads();
#pragma unroll
        for (int k = 0; k < BK; k++) {
            float ra[8], rb[4];
#pragma unroll
            for (int i = 0; i < 8; i++) ra[i] = As[k][ty * 8 + i];
#pragma unroll
            for (int j = 0; j < 4; j++) rb[j] = Bs[k][tx * 4 + j];
#pragma unroll
            for (int i = 0; i < 8; i++)
#pragma unroll
                for (int j = 0; j < 4; j++) acc[i][j] = fmaf(ra[i], rb[j], acc[i][j]);
        }
    }

    float4 bv = ((const float4*)bias)[bx * 16 + tx];
#pragma unroll
    for (int i = 0; i < 8; i++) {
        int row = by * BM + ty * 8 + i;
        float4 v;
        v.x = acc[i][0] + bv.x; v.y = acc[i][1] + bv.y;
        v.z = acc[i][2] + bv.z; v.w = acc[i][3] + bv.w;
        ((float4*)(C + (size_t)row * N))[bx * 16 + tx] = v;
    }
}

// =================================================================
// transpose + fp16 convert (z==0); adjacency bit-pack (z==1)
// =================================================================
__global__ __launch_bounds__(256) void transpose_pack(
    const float* __restrict__ h, __half* __restrict__ hT, int F,
    const int* __restrict__ adj, uint32_t* __restrict__ bits)
{
    if (blockIdx.z == 1) {
        int bid = blockIdx.x + blockIdx.y * gridDim.x;
        int wd = threadIdx.x;
#pragma unroll
        for (int r = 0; r < 4; r++) {
            int row = bid * 4 + r;
            const int4* src = (const int4*)(adj + (size_t)row * NN + wd * 32);
            uint32_t m = 0;
#pragma unroll
            for (int q = 0; q < 8; q++) {
                int4 v = src[q];
                m |= (v.x != 0 ? 1u : 0u) << (q * 4 + 0);
                m |= (v.y != 0 ? 1u : 0u) << (q * 4 + 1);
                m |= (v.z != 0 ? 1u : 0u) << (q * 4 + 2);
                m |= (v.w != 0 ? 1u : 0u) << (q * 4 + 3);
            }
            bits[(size_t)row * (NN / 32) + wd] = m;
        }
        return;
    }

    __shared__ float ts[32][33];
    int n0 = blockIdx.x * 32, c0 = blockIdx.y * 32;
    int r = threadIdx.x >> 3, cc = (threadIdx.x & 7) * 4;

    float4 v = *(const float4*)(h + (size_t)(n0 + r) * F + c0 + cc);
    ts[r][cc + 0] = v.x; ts[r][cc + 1] = v.y;
    ts[r][cc + 2] = v.z; ts[r][cc + 3] = v.w;
    __syncthreads();

    int c = threadIdx.x >> 3, nn2 = (threadIdx.x & 7) * 4;
    __half2 p0 = __floats2half2_rn(ts[nn2 + 0][c], ts[nn2 + 1][c]);
    __half2 p1 = __floats2half2_rn(ts[nn2 + 2][c], ts[nn2 + 3][c]);
    union { __half2 h2[2]; uint2 u; } cv;
    cv.h2[0] = p0; cv.h2[1] = p1;
    *(uint2*)(hT + (size_t)(c0 + c) * NN + n0 + nn2) = cv.u;
}

// =================================================================
// s/t projections + E12 table + block-reduced atomicMax of t
// =================================================================
template <int F>
__global__ __launch_bounds__(256) void st_kernel(
    const float* __restrict__ h, const float* __restrict__ a,
    float* __restrict__ s, float* __restrict__ t,
    float* __restrict__ E12, int* __restrict__ tmax)
{
    __shared__ float wmax[8];
    int warp = threadIdx.x >> 5, lane = threadIdx.x & 31;
    int row = blockIdx.x * 8 + warp;
    const float* hr = h + (size_t)row * F;
    float lo = 0.f, hi = 0.f;
#pragma unroll
    for (int f = lane; f < F; f += 32) {
        float v = hr[f];
        lo = fmaf(v, a[f], lo);
        hi = fmaf(v, a[F + f], hi);
    }
#pragma unroll
    for (int o = 16; o; o >>= 1) {
        lo += __shfl_xor_sync(0xffffffffu, lo, o);
        hi += __shfl_xor_sync(0xffffffffu, hi, o);
    }
    if (lane == 0) {
        s[row] = lo; t[row] = hi;
        E12[2 * row] = __expf(hi);
        E12[2 * row + 1] = __expf(LRELU_A * hi);
        wmax[warp] = hi;
    }
    __syncthreads();
    if (threadIdx.x == 0) {
        float m = wmax[0];
#pragma unroll
        for (int q = 1; q < 8; q++) m = fmaxf(m, wmax[q]);
        atomicMax(tmax, enc_f(m));
    }
}

// =================================================================
// Fused GAT attention (partial): fp16 mma.sync + cp.async + ldmatrix.
// BM rows x NFB cols per CTA, NTH threads, TPI 64-j subtiles/iter,
// SPLITJ-way j-split. Writes RAW partial acc + l to scratch.
// E12 + adj bits PREFETCHED into registers at iteration start so the
// L2 latency drains under the mma phase.
// =================================================================
template <int NF, int NFB, int BM, int NTH, int TPI, int SPLITJ, int MINB>
__global__ __launch_bounds__(NTH, MINB) void attn_mma(
    const __half* __restrict__ hTg, const uint32_t* __restrict__ bits,
    const float* __restrict__ sG, const float* __restrict__ abG,
    const int* __restrict__ tmaxI, const float* __restrict__ E12g,
    float* __restrict__ paccG, float* __restrict__ plG)
{
    constexpr int NW = NTH / 32;
    constexpr int WR = BM / 16;
    constexpr int WC = NW / WR;
    constexpr int PERCOL = NFB / WC;
    constexpr int NCT = PERCOL / 8;
    constexpr int NQ = NCT / 2;
    constexpr int THT = NFB * 128;
    constexpr int TPS = BM * 128;
    constexpr int HTB = TPI * THT;
    constexpr int PSB = TPI * TPS;
    constexpr int PERT = NFB * 8 / NTH;
    constexpr int NIT = NN / (64 * TPI * SPLITJ);
    constexpr int NBLK = NF / NFB;
    constexpr int ROWDIV = NBLK * SPLITJ;

    extern __shared__ char smem[];
    const uint32_t sb = (uint32_t)__cvta_generic_to_shared(smem);

    const int tid = threadIdx.x;
    const int lane = tid & 31, w = tid >> 5;
    const int g = lane >> 2, tig = lane & 3;
    const int wr = w / WC, wc = w % WC;
    const int R0 = wr * 16, C0 = wc * PERCOL;
    const int bid = blockIdx.x;
    const int rb = bid / ROWDIV;
    const int r2 = bid % ROWDIV;
    const int cb = r2 / SPLITJ;
    const int jh = r2 % SPLITJ;
    const int i0 = rb * BM, c0 = cb * NFB;
    const int jbase = jh * (NN / SPLITJ);

    // phase-A mapping: 8 threads per row, 8 j per thread per subtile
    const int ar = tid >> 3, acg = tid & 7;
    const float svp = sG[i0 + ar] + abG[0];
    const float Ma = svp + dec_f(tmaxI[0]);
    const float M = fmaxf(Ma, LRELU_A * Ma);
    const float c1 = __expf(svp - M);
    const float c2 = __expf(LRELU_A * svp - M);
    const float c3 = __expf(-svp);
    float lacc = 0.f;

    float acc[NCT][4];
#pragma unroll
    for (int c = 0; c < NCT; c++)
#pragma unroll
        for (int q = 0; q < 4; q++) acc[c][q] = 0.f;

    const uint32_t* brow = bits + (size_t)(i0 + ar) * (NN / 32);
    const int bsh = (acg & 3) * 8;
    const uint32_t xr = (uint32_t)((ar & 7) << 4);
    const uint32_t xO = (uint32_t)((lane & 7) << 4);
    const uint32_t aBoff = (uint32_t)((lane >> 4) << 4);
    const int bColB = (lane & 7) + ((lane >> 4) << 3);
    const uint32_t bBoff = (uint32_t)(((lane >> 3) & 1) << 4);
    const int aRowB = R0 + (lane & 7) + ((lane >> 3) & 1) * 8;

    uint32_t aOffA[4], bOffA[4];
#pragma unroll
    for (int k = 0; k < 4; k++) {
        aOffA[k] = (((uint32_t)(32 * k)) + aBoff) ^ xO;
        bOffA[k] = (((uint32_t)(32 * k)) + bBoff) ^ xO;
    }
    const uint32_t cBase = (uint32_t)(C0 + bColB) * 128;
    const uint32_t psB0 = sb + 2 * HTB + (uint32_t)aRowB * 128;

    uint32_t bwv[TPI];
    float4 evv[TPI][4];          // prefetched E12: 8 j-cols x (E1,E2) per subtile

#define ISSUE_CP(J0, BUF) do {                                                 \
    uint32_t hb = sb + (BUF) * HTB;                                            \
    _Pragma("unroll")                                                          \
    for (int tp = 0; tp < TPI; tp++) {                                         \
        _Pragma("unroll")                                                      \
        for (int u = 0; u < PERT; u++) {                                       \
            int ci = tid * PERT + u;                                           \
            int rr = ci >> 3, ch = ci & 7;                                     \
            uint32_t dst = hb + tp * THT + rr * 128 +                          \
                           (((uint32_t)(ch * 16)) ^ (((uint32_t)(rr & 7)) << 4)); \
            cp16(dst, hTg + (size_t)(c0 + rr) * NN + (J0) + tp * 64 + ch * 8); \
        }                                                                      \
    }                                                                          \
    asm volatile("cp.async.commit_group;" ::: "memory");                       \
} while (0)

#define LOAD_PF(J0) do {                                                       \
    _Pragma("unroll")                                                          \
    for (int tp = 0; tp < TPI; tp++) {                                         \
        bwv[tp] = brow[(((J0) + tp * 64) >> 5) + (acg >> 2)];                  \
        const float4* ep = (const float4*)(E12g + 2 * ((J0) + tp * 64 + acg * 8)); \
        evv[tp][0] = ep[0]; evv[tp][1] = ep[1];                                \
        evv[tp][2] = ep[2]; evv[tp][3] = ep[3];                                \
    }                                                                          \
} while (0)

#define PHASE_A(BUF) do {                                                      \
    _Pragma("unroll")                                                          \
    for (int tp = 0; tp < TPI; tp++) {                                         \
        uint32_t mb = bwv[tp] >> bsh;                                          \
        union { __half2 h2[4]; uint4 u; } cvv;                                 \
        _Pragma("unroll")                                                      \
        for (int q = 0; q < 4; q++) {                                          \
            float4 v = evv[tp][q];                                             \
            float p0 = (v.x >= c3) ? c1 * v.x : c2 * v.y;                      \
            p0 = ((mb >> (2 * q)) & 1u) ? p0 : 0.f;                            \
            float p1 = (v.z >= c3) ? c1 * v.z : c2 * v.w;                      \
            p1 = ((mb >> (2 * q + 1)) & 1u) ? p1 : 0.f;                        \
            lacc += p0 + p1;                                                   \
            cvv.h2[q] = __floats2half2_rn(p0, p1);                             \
        }                                                                      \
        char* pbase = smem + 2 * HTB + (BUF) * PSB + tp * TPS + ar * 128;      \
        *(uint4*)(pbase + (((uint32_t)(acg * 16)) ^ xr)) = cvv.u;              \
    }                                                                          \
} while (0)

    // ---- prologue ----
    ISSUE_CP(jbase, 0);
    LOAD_PF(jbase);
    PHASE_A(0);

    for (int i = 0; i < NIT; i++) {
        asm volatile("cp.async.wait_group 0;" ::: "memory");
        __syncthreads();

        const int cbf = i & 1, nb = (i + 1) & 1;
        const int jn = jbase + (i + 1) * 64 * TPI;
        if (i + 1 < NIT) {
            ISSUE_CP(jn, nb);
            LOAD_PF(jn);
        }

        // ---- mma(i) with hoisted addresses (hides LOAD_PF latency) ----
        const uint32_t psA0 = psB0 + (uint32_t)cbf * PSB;
        const uint32_t htA0 = sb + (uint32_t)cbf * HTB + cBase;
#pragma unroll
        for (int tp = 0; tp < TPI; tp++) {
            const uint32_t psA = psA0 + tp * TPS;
            const uint32_t htA = htA0 + tp * THT;
#pragma unroll
            for (int k = 0; k < 4; k++) {
                uint32_t a0, a1, a2, a3;
                ldsm4(a0, a1, a2, a3, psA + aOffA[k]);
#pragma unroll
                for (int q = 0; q < NQ; q++) {
                    uint32_t b0, b1, b2, b3;
                    ldsm4(b0, b1, b2, b3, htA + (uint32_t)(q * 2048) + bOffA[k]);
                    mma16816(acc[2 * q + 0], a0, a1, a2, a3, b0, b1);
                    mma16816(acc[2 * q + 1], a0, a1, a2, a3, b2, b3);
                }
            }
        }

        if (i + 1 < NIT) PHASE_A(nb);
    }

    // ---- write partial l (once per row; cb==0 only) ----
    lacc += __shfl_xor_sync(0xffffffffu, lacc, 1);
    lacc += __shfl_xor_sync(0xffffffffu, lacc, 2);
    lacc += __shfl_xor_sync(0xffffffffu, lacc, 4);
    if (acg == 0 && cb == 0) plG[jh * NN + i0 + ar] = lacc;

    // ---- write raw partial acc ----
    const int r0 = i0 + R0 + g, r1 = i0 + R0 + 8 + g;
    float* pj = paccG + (size_t)jh * NN * NF;
#pragma unroll
    for (int ct = 0; ct < NCT; ct++) {
        int c = c0 + C0 + 8 * ct + 2 * tig;
        *(float2*)(pj + (size_t)r0 * NF + c) = make_float2(acc[ct][0], acc[ct][1]);
        *(float2*)(pj + (size_t)r1 * NF + c) = make_float2(acc[ct][2], acc[ct][3]);
    }
#undef ISSUE_CP
#undef LOAD_PF
#undef PHASE_A
}

// =================================================================
// combine (mid layer): y = elu(elu((p0+p1)/(l0+l1))), elementwise
// =================================================================
__global__ __launch_bounds__(256) void comb_mid(
    const float* __restrict__ pacc, const float* __restrict__ pl,
    float* __restrict__ y)
{
    int idx = blockIdx.x * 256 + threadIdx.x;       // float4 index
    int row = idx / (FH / 4);
    float inv = 1.f / (pl[row] + pl[NN + row]);
    float4 a = ((const float4*)pacc)[idx];
    float4 b = ((const float4*)pacc)[idx + NN * (FH / 4)];
    float4 o;
    o.x = elu1(elu1((a.x + b.x) * inv));
    o.y = elu1(elu1((a.y + b.y) * inv));
    o.z = elu1(elu1((a.z + b.z) * inv));
    o.w = elu1(elu1((a.w + b.w) * inv));
    ((float4*)y)[idx] = o;
}

// =================================================================
// combine (final): out = log_softmax(elu((p0+p1)/(l0+l1))), per row
// =================================================================
__global__ __launch_bounds__(256) void comb_fin(
    const float* __restrict__ pacc, const float* __restrict__ pl,
    float* __restrict__ out)
{
    int tid = threadIdx.x;
    int qr = tid >> 3, ql = tid & 7;
    int row = blockIdx.x * 32 + qr;
    float inv = 1.f / (pl[row] + pl[NN + row]);
    const float* a0 = pacc + (size_t)row * FOUT + ql * 8;
    const float* a1 = a0 + (size_t)NN * FOUT;
    float z[8];
    {
        float4 u0 = ((const float4*)a0)[0], u1 = ((const float4*)a0)[1];
        float4 v0 = ((const float4*)a1)[0], v1 = ((const float4*)a1)[1];
        z[0] = elu1((u0.x + v0.x) * inv); z[1] = elu1((u0.y + v0.y) * inv);
        z[2] = elu1((u0.z + v0.z) * inv); z[3] = elu1((u0.w + v0.w) * inv);
        z[4] = elu1((u1.x + v1.x) * inv); z[5] = elu1((u1.y + v1.y) * inv);
        z[6] = elu1((u1.z + v1.z) * inv); z[7] = elu1((u1.w + v1.w) * inv);
    }
    float mx = z[0];
#pragma unroll
    for (int i = 1; i < 8; i++) mx = fmaxf(mx, z[i]);
    mx = fmaxf(mx, __shfl_xor_sync(0xffffffffu, mx, 1));
    mx = fmaxf(mx, __shfl_xor_sync(0xffffffffu, mx, 2));
    mx = fmaxf(mx, __shfl_xor_sync(0xffffffffu, mx, 4));
    float se = 0.f;
#pragma unroll
    for (int i = 0; i < 8; i++) se += __expf(z[i] - mx);
    se += __shfl_xor_sync(0xffffffffu, se, 1);
    se += __shfl_xor_sync(0xffffffffu, se, 2);
    se += __shfl_xor_sync(0xffffffffu, se, 4);
    float lse = mx + logf(se);
    float4 o0 = make_float4(z[0] - lse, z[1] - lse, z[2] - lse, z[3] - lse);
    float4 o1 = make_float4(z[4] - lse, z[5] - lse, z[6] - lse, z[7] - lse);
    float* op = out + (size_t)row * FOUT + ql * 8;
    ((float4*)op)[0] = o0;
    ((float4*)op)[1] = o1;
}

// =================================================================
extern "C" void kernel_launch(void* const* d_in, const int* in_sizes, int n_in,
                              void* d_out, int out_size)
{
    const float* x   = (const float*)d_in[0];
    const int*   adj = (const int*)  d_in[1];
    const float* W1  = (const float*)d_in[2];
    const float* b1  = (const float*)d_in[3];
    const float* a1  = (const float*)d_in[4];
    const float* ab1 = (const float*)d_in[5];
    const float* W2  = (const float*)d_in[6];
    const float* b2  = (const float*)d_in[7];
    const float* a2  = (const float*)d_in[8];
    const float* ab2 = (const float*)d_in[9];
    float* out = (float*)d_out;

    void *h1p, *y1p, *h2p, *h1tp, *h2tp, *s1p, *t1p, *s2p, *t2p, *tmp, *abp,
         *e12p, *pap, *plp;
    cudaGetSymbolAddress(&h1p, g_h1);
    cudaGetSymbolAddress(&y1p, g_y1);
    cudaGetSymbolAddress(&h2p, g_h2);
    cudaGetSymbolAddress(&h1tp, g_h1T);
    cudaGetSymbolAddress(&h2tp, g_h2T);
    cudaGetSymbolAddress(&s1p, g_s1);
    cudaGetSymbolAddress(&t1p, g_t1);
    cudaGetSymbolAddress(&s2p, g_s2);
    cudaGetSymbolAddress(&t2p, g_t2);
    cudaGetSymbolAddress(&tmp, g_tmaxi);
    cudaGetSymbolAddress(&abp, g_adjbits);
    cudaGetSymbolAddress(&e12p, g_E12);
    cudaGetSymbolAddress(&pap, g_pacc);
    cudaGetSymbolAddress(&plp, g_pl);
    float* h1 = (float*)h1p; float* y1 = (float*)y1p; float* h2 = (float*)h2p;
    __half* h1T = (__half*)h1tp; __half* h2T = (__half*)h2tp;
    float* s1 = (float*)s1p; float* t1 = (float*)t1p;
    float* s2 = (float*)s2p; float* t2 = (float*)t2p;
    int* tmaxi = (int*)tmp;
    uint32_t* abits = (uint32_t*)abp;
    float* E12 = (float*)e12p;
    float* pacc = (float*)pap;
    float* pl = (float*)plp;

    // attn1: NFB=128, BM=32, 256thr, TPI=1, SPLITJ=2, 4 CTAs/SM  -> smem 40960
    // attn2: NFB=64,  BM=16, 128thr, TPI=2, SPLITJ=2, 5 CTAs/SM  -> smem 40960
    const int SM1 = 2 * (1 * 128 * 128) + 2 * (1 * 32 * 128);
    const int SM2 = 2 * (2 * 64 * 128) + 2 * (2 * 16 * 128);
    cudaFuncSetAttribute((const void*)attn_mma<FH, 128, 32, 256, 1, 2, 4>,
                         cudaFuncAttributeMaxDynamicSharedMemorySize, SM1);
    cudaFuncSetAttribute((const void*)attn_mma<FOUT, 64, 16, 128, 2, 2, 5>,
                         cudaFuncAttributeMaxDynamicSharedMemorySize, SM2);

    // Layer 1  (attn_mma is the 4th launch -> gets profiled by ncu)
    gemm_bias<<<dim3(FH / 64, NN / 128), 256>>>(x, W1, b1, h1, NN, FH, FIN);
    transpose_pack<<<dim3(NN / 32, FH / 32, 2), 256>>>(h1, h1T, FH, adj, abits);
    st_kernel<FH><<<NN / 8, 256>>>(h1, a1, s1, t1, E12, tmaxi);
    attn_mma<FH, 128, 32, 256, 1, 2, 4><<<(NN / 32) * 4, 256, SM1>>>(
        h1T, abits, s1, ab1, tmaxi, E12, pacc, pl);
    comb_mid<<<NN * FH / 4 / 256, 256>>>(pacc, pl, y1);

    // Layer 2
    gemm_bias<<<dim3(FOUT / 64, NN / 128), 256>>>(y1, W2, b2, h2, NN, FOUT, FH);
    transpose_pack<<<dim3(NN / 32, FOUT / 32, 1), 256>>>(h2, h2T, FOUT, adj, abits);
    st_kernel<FOUT><<<NN / 8, 256>>>(h2, a2, s2, t2, E12, tmaxi + 1);
    attn_mma<FOUT, 64, 16, 128, 2, 2, 5><<<(NN / 16) * 2, 128, SM2>>>(
        h2T, abits, s2, ab2, tmaxi + 1, E12, pacc, pl);
    comb_fin<<<NN / 32, 256>>>(pacc, pl, out);
}

// round 15
// speedup vs baseline: 1.1410x; 1.0223x over previous
#include <cuda_runtime.h>
#include <cuda_fp16.h>
#include <math.h>
#include <stdint.h>

#define NN 8192
#define FIN 512
#define FH 256
#define FOUT 64
#define LRELU_A 0.2f

// ---------------- scratch (no allocations allowed) ----------------
__device__ float g_h1[NN * FH];
__device__ float g_y1[NN * FH];
__device__ float g_h2[NN * FOUT];
__device__ __half g_h1T[FH * NN];
__device__ __half g_h2T[FOUT * NN];
__device__ float g_s1[NN], g_t1[NN];
__device__ float g_s2[NN], g_t2[NN];
__device__ int g_tmaxi[2];
__device__ uint32_t g_adjbits[(size_t)NN * (NN / 32)];
__device__ __align__(16) float g_E12[2 * NN];          // (exp(t), exp(0.2t)) per j
__device__ float g_pacc[2 * (size_t)NN * FH];          // split-j partial acc (reused)
__device__ float g_pl[2 * NN];                         // split-j partial l

__device__ __forceinline__ float elu1(float x) { return x > 0.f ? x : expm1f(x); }

__device__ __forceinline__ int enc_f(float f) {
    int i = __float_as_int(f);
    return i < 0 ? (i ^ 0x7fffffff) : i;
}
__device__ __forceinline__ float dec_f(int i) {
    return __int_as_float(i < 0 ? (i ^ 0x7fffffff) : i);
}

__device__ __forceinline__ void ldsm4(uint32_t& r0, uint32_t& r1, uint32_t& r2,
                                      uint32_t& r3, uint32_t addr) {
    asm volatile("ldmatrix.sync.aligned.m8n8.x4.shared.b16 {%0,%1,%2,%3}, [%4];"
                 : "=r"(r0), "=r"(r1), "=r"(r2), "=r"(r3) : "r"(addr));
}

__device__ __forceinline__ void mma16816(float d[4], uint32_t a0, uint32_t a1,
                                         uint32_t a2, uint32_t a3,
                                         uint32_t b0, uint32_t b1) {
    asm volatile(
        "mma.sync.aligned.m16n8k16.row.col.f32.f16.f16.f32 "
        "{%0,%1,%2,%3}, {%4,%5,%6,%7}, {%8,%9}, {%0,%1,%2,%3};"
        : "+f"(d[0]), "+f"(d[1]), "+f"(d[2]), "+f"(d[3])
        : "r"(a0), "r"(a1), "r"(a2), "r"(a3), "r"(b0), "r"(b1));
}

__device__ __forceinline__ void cp16(uint32_t dst, const void* src) {
    asm volatile("cp.async.cg.shared.global [%0], [%1], 16;" :: "r"(dst), "l"(src));
}

// =================================================================
// GEMM: C[M,N] = A[M,K] @ W[N,K]^T + bias[N]. Also re-inits tmax ints.
// =================================================================
__global__ __launch_bounds__(256) void gemm_bias(
    const float* __restrict__ A, const float* __restrict__ W,
    const float* __restrict__ bias, float* __restrict__ C,
    int M, int N, int K)
{
    const int BM = 128, BN = 64, BK = 16;
    __shared__ float As[BK][BM + 1];
    __shared__ float Bs[BK][BN + 1];

    int tid = threadIdx.x;
    int bx = blockIdx.x, by = blockIdx.y;
    if (bx == 0 && by == 0 && tid == 0) {
        g_tmaxi[0] = (int)0x80000000;
        g_tmaxi[1] = (int)0x80000000;
    }
    int ty = tid >> 4, tx = tid & 15;
    int ar = tid >> 2, ac4 = (tid & 3) * 4;

    float acc[8][4];
#pragma unroll
    for (int i = 0; i < 8; i++)
#pragma unroll
        for (int j = 0; j < 4; j++) acc[i][j] = 0.f;

    for (int k0 = 0; k0 < K; k0 += BK) {
        float4 a0 = *(const float4*)(A + (size_t)(by * BM + ar) * K + k0 + ac4);
        float4 a1 = *(const float4*)(A + (size_t)(by * BM + ar + 64) * K + k0 + ac4);
        float4 b0 = *(const float4*)(W + (size_t)(bx * BN + ar) * K + k0 + ac4);
        __syncthreads();
        As[ac4 + 0][ar] = a0.x; As[ac4 + 1][ar] = a0.y;
        As[ac4 + 2][ar] = a0.z; As[ac4 + 3][ar] = a0.w;
        As[ac4 + 0][ar + 64] = a1.x; As[ac4 + 1][ar + 64] = a1.y;
        As[ac4 + 2][ar + 64] = a1.z; As[ac4 + 3][ar + 64] = a1.w;
        Bs[ac4 + 0][ar] = b0.x; Bs[ac4 + 1][ar] = b0.y;
        Bs[ac4 + 2][ar] = b0.z; Bs[ac4 + 3][ar] = b0.w;
        __syncthreads();
#pragma unroll
        for (int k = 0; k < BK; k++) {
            float ra[8], rb[4];
#pragma unroll
            for (int i = 0; i < 8; i++) ra[i] = As[k][ty * 8 + i];
#pragma unroll
            for (int j = 0; j < 4; j++) rb[j] = Bs[k][tx * 4 + j];
#pragma unroll
            for (int i = 0; i < 8; i++)
#pragma unroll
                for (int j = 0; j < 4; j++) acc[i][j] = fmaf(ra[i], rb[j], acc[i][j]);
        }
    }

    float4 bv = ((const float4*)bias)[bx * 16 + tx];
#pragma unroll
    for (int i = 0; i < 8; i++) {
        int row = by * BM + ty * 8 + i;
        float4 v;
        v.x = acc[i][0] + bv.x; v.y = acc[i][1] + bv.y;
        v.z = acc[i][2] + bv.z; v.w = acc[i][3] + bv.w;
        ((float4*)(C + (size_t)row * N))[bx * 16 + tx] = v;
    }
}

// =================================================================
// transpose + fp16 convert (z==0); adjacency bit-pack (z==1)
// =================================================================
__global__ __launch_bounds__(256) void transpose_pack(
    const float* __restrict__ h, __half* __restrict__ hT, int F,
    const int* __restrict__ adj, uint32_t* __restrict__ bits)
{
    if (blockIdx.z == 1) {
        int bid = blockIdx.x + blockIdx.y * gridDim.x;
        int wd = threadIdx.x;
#pragma unroll
        for (int r = 0; r < 4; r++) {
            int row = bid * 4 + r;
            const int4* src = (const int4*)(adj + (size_t)row * NN + wd * 32);
            uint32_t m = 0;
#pragma unroll
            for (int q = 0; q < 8; q++) {
                int4 v = src[q];
                m |= (v.x != 0 ? 1u : 0u) << (q * 4 + 0);
                m |= (v.y != 0 ? 1u : 0u) << (q * 4 + 1);
                m |= (v.z != 0 ? 1u : 0u) << (q * 4 + 2);
                m |= (v.w != 0 ? 1u : 0u) << (q * 4 + 3);
            }
            bits[(size_t)row * (NN / 32) + wd] = m;
        }
        return;
    }

    __shared__ float ts[32][33];
    int n0 = blockIdx.x * 32, c0 = blockIdx.y * 32;
    int r = threadIdx.x >> 3, cc = (threadIdx.x & 7) * 4;

    float4 v = *(const float4*)(h + (size_t)(n0 + r) * F + c0 + cc);
    ts[r][cc + 0] = v.x; ts[r][cc + 1] = v.y;
    ts[r][cc + 2] = v.z; ts[r][cc + 3] = v.w;
    __syncthreads();

    int c = threadIdx.x >> 3, nn2 = (threadIdx.x & 7) * 4;
    __half2 p0 = __floats2half2_rn(ts[nn2 + 0][c], ts[nn2 + 1][c]);
    __half2 p1 = __floats2half2_rn(ts[nn2 + 2][c], ts[nn2 + 3][c]);
    union { __half2 h2[2]; uint2 u; } cv;
    cv.h2[0] = p0; cv.h2[1] = p1;
    *(uint2*)(hT + (size_t)(c0 + c) * NN + n0 + nn2) = cv.u;
}

// =================================================================
// s/t projections + E12 table + block-reduced atomicMax of t
// =================================================================
template <int F>
__global__ __launch_bounds__(256) void st_kernel(
    const float* __restrict__ h, const float* __restrict__ a,
    float* __restrict__ s, float* __restrict__ t,
    float* __restrict__ E12, int* __restrict__ tmax)
{
    __shared__ float wmax[8];
    int warp = threadIdx.x >> 5, lane = threadIdx.x & 31;
    int row = blockIdx.x * 8 + warp;
    const float* hr = h + (size_t)row * F;
    float lo = 0.f, hi = 0.f;
#pragma unroll
    for (int f = lane; f < F; f += 32) {
        float v = hr[f];
        lo = fmaf(v, a[f], lo);
        hi = fmaf(v, a[F + f], hi);
    }
#pragma unroll
    for (int o = 16; o; o >>= 1) {
        lo += __shfl_xor_sync(0xffffffffu, lo, o);
        hi += __shfl_xor_sync(0xffffffffu, hi, o);
    }
    if (lane == 0) {
        s[row] = lo; t[row] = hi;
        E12[2 * row] = __expf(hi);
        E12[2 * row + 1] = __expf(LRELU_A * hi);
        wmax[warp] = hi;
    }
    __syncthreads();
    if (threadIdx.x == 0) {
        float m = wmax[0];
#pragma unroll
        for (int q = 1; q < 8; q++) m = fmaxf(m, wmax[q]);
        atomicMax(tmax, enc_f(m));
    }
}

// =================================================================
// Fused GAT attention (partial): fp16 mma.sync + cp.async + ldmatrix.
// BM rows x NFB cols per CTA, NTH threads, TPI 64-j subtiles/iter,
// SPLITJ-way j-split. Writes RAW partial acc + l to scratch.
// Phase A uses factored exp: p = (E1 >= c3) ? c1*E1 : c2*E2.
// =================================================================
template <int NF, int NFB, int BM, int NTH, int TPI, int SPLITJ, int MINB>
__global__ __launch_bounds__(NTH, MINB) void attn_mma(
    const __half* __restrict__ hTg, const uint32_t* __restrict__ bits,
    const float* __restrict__ sG, const float* __restrict__ abG,
    const int* __restrict__ tmaxI, const float* __restrict__ E12g,
    float* __restrict__ paccG, float* __restrict__ plG)
{
    constexpr int NW = NTH / 32;
    constexpr int WR = BM / 16;
    constexpr int WC = NW / WR;
    constexpr int PERCOL = NFB / WC;
    constexpr int NCT = PERCOL / 8;
    constexpr int NQ = NCT / 2;
    constexpr int THT = NFB * 128;
    constexpr int TPS = BM * 128;
    constexpr int HTB = TPI * THT;
    constexpr int PSB = TPI * TPS;
    constexpr int PERT = NFB * 8 / NTH;
    constexpr int NIT = NN / (64 * TPI * SPLITJ);
    constexpr int NBLK = NF / NFB;
    constexpr int ROWDIV = NBLK * SPLITJ;

    extern __shared__ char smem[];
    const uint32_t sb = (uint32_t)__cvta_generic_to_shared(smem);

    const int tid = threadIdx.x;
    const int lane = tid & 31, w = tid >> 5;
    const int g = lane >> 2, tig = lane & 3;
    const int wr = w / WC, wc = w % WC;
    const int R0 = wr * 16, C0 = wc * PERCOL;
    const int bid = blockIdx.x;
    const int rb = bid / ROWDIV;
    const int r2 = bid % ROWDIV;
    const int cb = r2 / SPLITJ;
    const int jh = r2 % SPLITJ;
    const int i0 = rb * BM, c0 = cb * NFB;
    const int jbase = jh * (NN / SPLITJ);

    // phase-A mapping: 8 threads per row, 8 j per thread per subtile
    const int ar = tid >> 3, acg = tid & 7;
    const float svp = sG[i0 + ar] + abG[0];
    const float Ma = svp + dec_f(tmaxI[0]);
    const float M = fmaxf(Ma, LRELU_A * Ma);
    const float c1 = __expf(svp - M);
    const float c2 = __expf(LRELU_A * svp - M);
    const float c3 = __expf(-svp);
    float lacc = 0.f;

    float acc[NCT][4];
#pragma unroll
    for (int c = 0; c < NCT; c++)
#pragma unroll
        for (int q = 0; q < 4; q++) acc[c][q] = 0.f;

    const uint32_t* brow = bits + (size_t)(i0 + ar) * (NN / 32);
    const int bsh = (acg & 3) * 8;
    const uint32_t xr = (uint32_t)((ar & 7) << 4);
    const uint32_t xO = (uint32_t)((lane & 7) << 4);
    const uint32_t aBoff = (uint32_t)((lane >> 4) << 4);
    const int bColB = (lane & 7) + ((lane >> 4) << 3);
    const uint32_t bBoff = (uint32_t)(((lane >> 3) & 1) << 4);
    const int aRowB = R0 + (lane & 7) + ((lane >> 3) & 1) * 8;

    uint32_t aOffA[4], bOffA[4];
#pragma unroll
    for (int k = 0; k < 4; k++) {
        aOffA[k] = (((uint32_t)(32 * k)) + aBoff) ^ xO;
        bOffA[k] = (((uint32_t)(32 * k)) + bBoff) ^ xO;
    }
    const uint32_t cBase = (uint32_t)(C0 + bColB) * 128;
    const uint32_t psB0 = sb + 2 * HTB + (uint32_t)aRowB * 128;

    uint32_t bwv[TPI];

#define ISSUE_CP(J0, BUF) do {                                                 \
    uint32_t hb = sb + (BUF) * HTB;                                            \
    _Pragma("unroll")                                                          \
    for (int tp = 0; tp < TPI; tp++) {                                         \
        _Pragma("unroll")                                                      \
        for (int u = 0; u < PERT; u++) {                                       \
            int ci = tid * PERT + u;                                           \
            int rr = ci >> 3, ch = ci & 7;                                     \
            uint32_t dst = hb + tp * THT + rr * 128 +                          \
                           (((uint32_t)(ch * 16)) ^ (((uint32_t)(rr & 7)) << 4)); \
            cp16(dst, hTg + (size_t)(c0 + rr) * NN + (J0) + tp * 64 + ch * 8); \
        }                                                                      \
    }                                                                          \
    asm volatile("cp.async.commit_group;" ::: "memory");                       \
} while (0)

#define LOAD_BITS(J0) do {                                                     \
    _Pragma("unroll")                                                          \
    for (int tp = 0; tp < TPI; tp++)                                           \
        bwv[tp] = brow[(((J0) + tp * 64) >> 5) + (acg >> 2)];                  \
} while (0)

#define PHASE_A(BUF, J0) do {                                                  \
    _Pragma("unroll")                                                          \
    for (int tp = 0; tp < TPI; tp++) {                                         \
        const float4* ep = (const float4*)(E12g + 2 * ((J0) + tp * 64 + acg * 8)); \
        float4 e0 = ep[0], e1 = ep[1], e2 = ep[2], e3 = ep[3];                 \
        float E1v[8] = {e0.x, e0.z, e1.x, e1.z, e2.x, e2.z, e3.x, e3.z};       \
        float E2v[8] = {e0.y, e0.w, e1.y, e1.w, e2.y, e2.w, e3.y, e3.w};       \
        uint32_t mb = bwv[tp] >> bsh;                                          \
        float p[8];                                                            \
        _Pragma("unroll")                                                      \
        for (int k2 = 0; k2 < 8; k2++) {                                       \
            float pv = (E1v[k2] >= c3) ? c1 * E1v[k2] : c2 * E2v[k2];          \
            pv = ((mb >> k2) & 1u) ? pv : 0.f;                                 \
            lacc += pv; p[k2] = pv;                                            \
        }                                                                      \
        union { __half2 h2[4]; uint4 u; } cvv;                                 \
        _Pragma("unroll")                                                      \
        for (int m2 = 0; m2 < 4; m2++)                                         \
            cvv.h2[m2] = __floats2half2_rn(p[2 * m2], p[2 * m2 + 1]);          \
        char* pbase = smem + 2 * HTB + (BUF) * PSB + tp * TPS + ar * 128;      \
        *(uint4*)(pbase + (((uint32_t)(acg * 16)) ^ xr)) = cvv.u;              \
    }                                                                          \
} while (0)

    // ---- prologue ----
    ISSUE_CP(jbase, 0);
    LOAD_BITS(jbase);
    PHASE_A(0, jbase);

    for (int i = 0; i < NIT; i++) {
        asm volatile("cp.async.wait_group 0;" ::: "memory");
        __syncthreads();

        const int cbf = i & 1, nb = (i + 1) & 1;
        const int jn = jbase + (i + 1) * 64 * TPI;
        if (i + 1 < NIT) {
            ISSUE_CP(jn, nb);
            LOAD_BITS(jn);
        }

        // ---- mma(i) with hoisted addresses ----
        const uint32_t psA0 = psB0 + (uint32_t)cbf * PSB;
        const uint32_t htA0 = sb + (uint32_t)cbf * HTB + cBase;
#pragma unroll
        for (int tp = 0; tp < TPI; tp++) {
            const uint32_t psA = psA0 + tp * TPS;
            const uint32_t htA = htA0 + tp * THT;
#pragma unroll
            for (int k = 0; k < 4; k++) {
                uint32_t a0, a1, a2, a3;
                ldsm4(a0, a1, a2, a3, psA + aOffA[k]);
#pragma unroll
                for (int q = 0; q < NQ; q++) {
                    uint32_t b0, b1, b2, b3;
                    ldsm4(b0, b1, b2, b3, htA + (uint32_t)(q * 2048) + bOffA[k]);
                    mma16816(acc[2 * q + 0], a0, a1, a2, a3, b0, b1);
                    mma16816(acc[2 * q + 1], a0, a1, a2, a3, b2, b3);
                }
            }
        }

        if (i + 1 < NIT) PHASE_A(nb, jn);
    }

    // ---- write partial l (once per row; cb==0 only) ----
    lacc += __shfl_xor_sync(0xffffffffu, lacc, 1);
    lacc += __shfl_xor_sync(0xffffffffu, lacc, 2);
    lacc += __shfl_xor_sync(0xffffffffu, lacc, 4);
    if (acg == 0 && cb == 0) plG[jh * NN + i0 + ar] = lacc;

    // ---- write raw partial acc ----
    const int r0 = i0 + R0 + g, r1 = i0 + R0 + 8 + g;
    float* pj = paccG + (size_t)jh * NN * NF;
#pragma unroll
    for (int ct = 0; ct < NCT; ct++) {
        int c = c0 + C0 + 8 * ct + 2 * tig;
        *(float2*)(pj + (size_t)r0 * NF + c) = make_float2(acc[ct][0], acc[ct][1]);
        *(float2*)(pj + (size_t)r1 * NF + c) = make_float2(acc[ct][2], acc[ct][3]);
    }
#undef ISSUE_CP
#undef LOAD_BITS
#undef PHASE_A
}

// =================================================================
// combine (mid layer): y = elu(elu((p0+p1)/(l0+l1))), elementwise
// =================================================================
__global__ __launch_bounds__(256) void comb_mid(
    const float* __restrict__ pacc, const float* __restrict__ pl,
    float* __restrict__ y)
{
    int idx = blockIdx.x * 256 + threadIdx.x;       // float4 index
    int row = idx / (FH / 4);
    float inv = 1.f / (pl[row] + pl[NN + row]);
    float4 a = ((const float4*)pacc)[idx];
    float4 b = ((const float4*)pacc)[idx + NN * (FH / 4)];
    float4 o;
    o.x = elu1(elu1((a.x + b.x) * inv));
    o.y = elu1(elu1((a.y + b.y) * inv));
    o.z = elu1(elu1((a.z + b.z) * inv));
    o.w = elu1(elu1((a.w + b.w) * inv));
    ((float4*)y)[idx] = o;
}

// =================================================================
// combine (final): out = log_softmax(elu((p0+p1)/(l0+l1))), per row
// =================================================================
__global__ __launch_bounds__(256) void comb_fin(
    const float* __restrict__ pacc, const float* __restrict__ pl,
    float* __restrict__ out)
{
    int tid = threadIdx.x;
    int qr = tid >> 3, ql = tid & 7;
    int row = blockIdx.x * 32 + qr;
    float inv = 1.f / (pl[row] + pl[NN + row]);
    const float* a0 = pacc + (size_t)row * FOUT + ql * 8;
    const float* a1 = a0 + (size_t)NN * FOUT;
    float z[8];
    {
        float4 u0 = ((const float4*)a0)[0], u1 = ((const float4*)a0)[1];
        float4 v0 = ((const float4*)a1)[0], v1 = ((const float4*)a1)[1];
        z[0] = elu1((u0.x + v0.x) * inv); z[1] = elu1((u0.y + v0.y) * inv);
        z[2] = elu1((u0.z + v0.z) * inv); z[3] = elu1((u0.w + v0.w) * inv);
        z[4] = elu1((u1.x + v1.x) * inv); z[5] = elu1((u1.y + v1.y) * inv);
        z[6] = elu1((u1.z + v1.z) * inv); z[7] = elu1((u1.w + v1.w) * inv);
    }
    float mx = z[0];
#pragma unroll
    for (int i = 1; i < 8; i++) mx = fmaxf(mx, z[i]);
    mx = fmaxf(mx, __shfl_xor_sync(0xffffffffu, mx, 1));
    mx = fmaxf(mx, __shfl_xor_sync(0xffffffffu, mx, 2));
    mx = fmaxf(mx, __shfl_xor_sync(0xffffffffu, mx, 4));
    float se = 0.f;
#pragma unroll
    for (int i = 0; i < 8; i++) se += __expf(z[i] - mx);
    se += __shfl_xor_sync(0xffffffffu, se, 1);
    se += __shfl_xor_sync(0xffffffffu, se, 2);
    se += __shfl_xor_sync(0xffffffffu, se, 4);
    float lse = mx + logf(se);
    float4 o0 = make_float4(z[0] - lse, z[1] - lse, z[2] - lse, z[3] - lse);
    float4 o1 = make_float4(z[4] - lse, z[5] - lse, z[6] - lse, z[7] - lse);
    float* op = out + (size_t)row * FOUT + ql * 8;
    ((float4*)op)[0] = o0;
    ((float4*)op)[1] = o1;
}

// =================================================================
extern "C" void kernel_launch(void* const* d_in, const int* in_sizes, int n_in,
                              void* d_out, int out_size)
{
    const float* x   = (const float*)d_in[0];
    const int*   adj = (const int*)  d_in[1];
    const float* W1  = (const float*)d_in[2];
    const float* b1  = (const float*)d_in[3];
    const float* a1  = (const float*)d_in[4];
    const float* ab1 = (const float*)d_in[5];
    const float* W2  = (const float*)d_in[6];
    const float* b2  = (const float*)d_in[7];
    const float* a2  = (const float*)d_in[8];
    const float* ab2 = (const float*)d_in[9];
    float* out = (float*)d_out;

    void *h1p, *y1p, *h2p, *h1tp, *h2tp, *s1p, *t1p, *s2p, *t2p, *tmp, *abp,
         *e12p, *pap, *plp;
    cudaGetSymbolAddress(&h1p, g_h1);
    cudaGetSymbolAddress(&y1p, g_y1);
    cudaGetSymbolAddress(&h2p, g_h2);
    cudaGetSymbolAddress(&h1tp, g_h1T);
    cudaGetSymbolAddress(&h2tp, g_h2T);
    cudaGetSymbolAddress(&s1p, g_s1);
    cudaGetSymbolAddress(&t1p, g_t1);
    cudaGetSymbolAddress(&s2p, g_s2);
    cudaGetSymbolAddress(&t2p, g_t2);
    cudaGetSymbolAddress(&tmp, g_tmaxi);
    cudaGetSymbolAddress(&abp, g_adjbits);
    cudaGetSymbolAddress(&e12p, g_E12);
    cudaGetSymbolAddress(&pap, g_pacc);
    cudaGetSymbolAddress(&plp, g_pl);
    float* h1 = (float*)h1p; float* y1 = (float*)y1p; float* h2 = (float*)h2p;
    __half* h1T = (__half*)h1tp; __half* h2T = (__half*)h2tp;
    float* s1 = (float*)s1p; float* t1 = (float*)t1p;
    float* s2 = (float*)s2p; float* t2 = (float*)t2p;
    int* tmaxi = (int*)tmp;
    uint32_t* abits = (uint32_t*)abp;
    float* E12 = (float*)e12p;
    float* pacc = (float*)pap;
    float* pl = (float*)plp;

    // attn1: NFB=128, BM=32, 256thr, TPI=1, SPLITJ=2, 4 CTAs/SM  -> smem 40960
    // attn2: NFB=64,  BM=16, 128thr, TPI=1, SPLITJ=2, 8 CTAs/SM  -> smem 20480
    const int SM1 = 2 * (1 * 128 * 128) + 2 * (1 * 32 * 128);
    const int SM2 = 2 * (1 * 64 * 128) + 2 * (1 * 16 * 128);
    cudaFuncSetAttribute((const void*)attn_mma<FH, 128, 32, 256, 1, 2, 4>,
                         cudaFuncAttributeMaxDynamicSharedMemorySize, SM1);
    cudaFuncSetAttribute((const void*)attn_mma<FOUT, 64, 16, 128, 1, 2, 8>,
                         cudaFuncAttributeMaxDynamicSharedMemorySize, SM2);

    // Layer 1  (attn_mma is the 4th launch -> gets profiled by ncu)
    gemm_bias<<<dim3(FH / 64, NN / 128), 256>>>(x, W1, b1, h1, NN, FH, FIN);
    transpose_pack<<<dim3(NN / 32, FH / 32, 2), 256>>>(h1, h1T, FH, adj, abits);
    st_kernel<FH><<<NN / 8, 256>>>(h1, a1, s1, t1, E12, tmaxi);
    attn_mma<FH, 128, 32, 256, 1, 2, 4><<<(NN / 32) * 4, 256, SM1>>>(
        h1T, abits, s1, ab1, tmaxi, E12, pacc, pl);
    comb_mid<<<NN * FH / 4 / 256, 256>>>(pacc, pl, y1);

    // Layer 2
    gemm_bias<<<dim3(FOUT / 64, NN / 128), 256>>>(y1, W2, b2, h2, NN, FOUT, FH);
    transpose_pack<<<dim3(NN / 32, FOUT / 32, 1), 256>>>(h2, h2T, FOUT, adj, abits);
    st_kernel<FOUT><<<NN / 8, 256>>>(h2, a2, s2, t2, E12, tmaxi + 1);
    attn_mma<FOUT, 64, 16, 128, 1, 2, 8><<<(NN / 16) * 2, 128, SM2>>>(
        h2T, abits, s2, ab2, tmaxi + 1, E12, pacc, pl);
    comb_fin<<<NN / 32, 256>>>(pacc, pl, out);
}

// round 16
// speedup vs baseline: 1.4833x; 1.3000x over previous
#include <cuda_runtime.h>
#include <cuda_fp16.h>
#include <math.h>
#include <stdint.h>

#define NN 8192
#define FIN 512
#define FH 256
#define FOUT 64
#define LRELU_A 0.2f

// ---------------- scratch (no allocations allowed) ----------------
__device__ float g_h1[NN * FH];
__device__ float g_y1[NN * FH];
__device__ float g_h2[NN * FOUT];
__device__ __half g_h1T[FH * NN];
__device__ __half g_h2T[FOUT * NN];
__device__ float g_s1[NN], g_t1[NN];
__device__ float g_s2[NN], g_t2[NN];
__device__ int g_tmaxi[2];
__device__ uint32_t g_adjbits[(size_t)NN * (NN / 32)];
__device__ __align__(16) float g_E12[2 * NN];          // (exp(t), exp(0.2t)) per j
__device__ float g_pacc[2 * (size_t)NN * FH];          // split-j partial acc (reused)
__device__ float g_pl[2 * NN];                         // split-j partial l

__device__ __forceinline__ float elu1(float x) { return x > 0.f ? x : expm1f(x); }

__device__ __forceinline__ int enc_f(float f) {
    int i = __float_as_int(f);
    return i < 0 ? (i ^ 0x7fffffff) : i;
}
__device__ __forceinline__ float dec_f(int i) {
    return __int_as_float(i < 0 ? (i ^ 0x7fffffff) : i);
}

__device__ __forceinline__ void ldsm4(uint32_t& r0, uint32_t& r1, uint32_t& r2,
                                      uint32_t& r3, uint32_t addr) {
    asm volatile("ldmatrix.sync.aligned.m8n8.x4.shared.b16 {%0,%1,%2,%3}, [%4];"
                 : "=r"(r0), "=r"(r1), "=r"(r2), "=r"(r3) : "r"(addr));
}

__device__ __forceinline__ void mma16816(float d[4], uint32_t a0, uint32_t a1,
                                         uint32_t a2, uint32_t a3,
                                         uint32_t b0, uint32_t b1) {
    asm volatile(
        "mma.sync.aligned.m16n8k16.row.col.f32.f16.f16.f32 "
        "{%0,%1,%2,%3}, {%4,%5,%6,%7}, {%8,%9}, {%0,%1,%2,%3};"
        : "+f"(d[0]), "+f"(d[1]), "+f"(d[2]), "+f"(d[3])
        : "r"(a0), "r"(a1), "r"(a2), "r"(a3), "r"(b0), "r"(b1));
}

__device__ __forceinline__ void cp16(uint32_t dst, const void* src) {
    asm volatile("cp.async.cg.shared.global [%0], [%1], 16;" :: "r"(dst), "l"(src));
}

// =================================================================
// GEMM: C[M,N] = A[M,K] @ W[N,K]^T + bias[N]. Also re-inits tmax ints.
// =================================================================
__global__ __launch_bounds__(256) void gemm_bias(
    const float* __restrict__ A, const float* __restrict__ W,
    const float* __restrict__ bias, float* __restrict__ C,
    int M, int N, int K)
{
    const int BM = 128, BN = 64, BK = 16;
    __shared__ float As[BK][BM + 1];
    __shared__ float Bs[BK][BN + 1];

    int tid = threadIdx.x;
    int bx = blockIdx.x, by = blockIdx.y;
    if (bx == 0 && by == 0 && tid == 0) {
        g_tmaxi[0] = (int)0x80000000;
        g_tmaxi[1] = (int)0x80000000;
    }
    int ty = tid >> 4, tx = tid & 15;
    int ar = tid >> 2, ac4 = (tid & 3) * 4;

    float acc[8][4];
#pragma unroll
    for (int i = 0; i < 8; i++)
#pragma unroll
        for (int j = 0; j < 4; j++) acc[i][j] = 0.f;

    for (int k0 = 0; k0 < K; k0 += BK) {
        float4 a0 = *(const float4*)(A + (size_t)(by * BM + ar) * K + k0 + ac4);
        float4 a1 = *(const float4*)(A + (size_t)(by * BM + ar + 64) * K + k0 + ac4);
        float4 b0 = *(const float4*)(W + (size_t)(bx * BN + ar) * K + k0 + ac4);
        __syncthreads();
        As[ac4 + 0][ar] = a0.x; As[ac4 + 1][ar] = a0.y;
        As[ac4 + 2][ar] = a0.z; As[ac4 + 3][ar] = a0.w;
        As[ac4 + 0][ar + 64] = a1.x; As[ac4 + 1][ar + 64] = a1.y;
        As[ac4 + 2][ar + 64] = a1.z; As[ac4 + 3][ar + 64] = a1.w;
        Bs[ac4 + 0][ar] = b0.x; Bs[ac4 + 1][ar] = b0.y;
        Bs[ac4 + 2][ar] = b0.z; Bs[ac4 + 3][ar] = b0.w;
        __syncthreads();
#pragma unroll
        for (int k = 0; k < BK; k++) {
            float ra[8], rb[4];
#pragma unroll
            for (int i = 0; i < 8; i++) ra[i] = As[k][ty * 8 + i];
#pragma unroll
            for (int j = 0; j < 4; j++) rb[j] = Bs[k][tx * 4 + j];
#pragma unroll
            for (int i = 0; i < 8; i++)
#pragma unroll
                for (int j = 0; j < 4; j++) acc[i][j] = fmaf(ra[i], rb[j], acc[i][j]);
        }
    }

    float4 bv = ((const float4*)bias)[bx * 16 + tx];
#pragma unroll
    for (int i = 0; i < 8; i++) {
        int row = by * BM + ty * 8 + i;
        float4 v;
        v.x = acc[i][0] + bv.x; v.y = acc[i][1] + bv.y;
        v.z = acc[i][2] + bv.z; v.w = acc[i][3] + bv.w;
        ((float4*)(C + (size_t)row * N))[bx * 16 + tx] = v;
    }
}

// =================================================================
// transpose + fp16 convert (z==0); adjacency bit-pack (z==1)
// =================================================================
__global__ __launch_bounds__(256) void transpose_pack(
    const float* __restrict__ h, __half* __restrict__ hT, int F,
    const int* __restrict__ adj, uint32_t* __restrict__ bits)
{
    if (blockIdx.z == 1) {
        int bid = blockIdx.x + blockIdx.y * gridDim.x;
        int wd = threadIdx.x;
#pragma unroll
        for (int r = 0; r < 4; r++) {
            int row = bid * 4 + r;
            const int4* src = (const int4*)(adj + (size_t)row * NN + wd * 32);
            uint32_t m = 0;
#pragma unroll
            for (int q = 0; q < 8; q++) {
                int4 v = src[q];
                m |= (v.x != 0 ? 1u : 0u) << (q * 4 + 0);
                m |= (v.y != 0 ? 1u : 0u) << (q * 4 + 1);
                m |= (v.z != 0 ? 1u : 0u) << (q * 4 + 2);
                m |= (v.w != 0 ? 1u : 0u) << (q * 4 + 3);
            }
            bits[(size_t)row * (NN / 32) + wd] = m;
        }
        return;
    }

    __shared__ float ts[32][33];
    int n0 = blockIdx.x * 32, c0 = blockIdx.y * 32;
    int r = threadIdx.x >> 3, cc = (threadIdx.x & 7) * 4;

    float4 v = *(const float4*)(h + (size_t)(n0 + r) * F + c0 + cc);
    ts[r][cc + 0] = v.x; ts[r][cc + 1] = v.y;
    ts[r][cc + 2] = v.z; ts[r][cc + 3] = v.w;
    __syncthreads();

    int c = threadIdx.x >> 3, nn2 = (threadIdx.x & 7) * 4;
    __half2 p0 = __floats2half2_rn(ts[nn2 + 0][c], ts[nn2 + 1][c]);
    __half2 p1 = __floats2half2_rn(ts[nn2 + 2][c], ts[nn2 + 3][c]);
    union { __half2 h2[2]; uint2 u; } cv;
    cv.h2[0] = p0; cv.h2[1] = p1;
    *(uint2*)(hT + (size_t)(c0 + c) * NN + n0 + nn2) = cv.u;
}

// =================================================================
// s/t projections + E12 table + block-reduced atomicMax of t
// =================================================================
template <int F>
__global__ __launch_bounds__(256) void st_kernel(
    const float* __restrict__ h, const float* __restrict__ a,
    float* __restrict__ s, float* __restrict__ t,
    float* __restrict__ E12, int* __restrict__ tmax)
{
    __shared__ float wmax[8];
    int warp = threadIdx.x >> 5, lane = threadIdx.x & 31;
    int row = blockIdx.x * 8 + warp;
    const float* hr = h + (size_t)row * F;
    float lo = 0.f, hi = 0.f;
#pragma unroll
    for (int f = lane; f < F; f += 32) {
        float v = hr[f];
        lo = fmaf(v, a[f], lo);
        hi = fmaf(v, a[F + f], hi);
    }
#pragma unroll
    for (int o = 16; o; o >>= 1) {
        lo += __shfl_xor_sync(0xffffffffu, lo, o);
        hi += __shfl_xor_sync(0xffffffffu, hi, o);
    }
    if (lane == 0) {
        s[row] = lo; t[row] = hi;
        E12[2 * row] = __expf(hi);
        E12[2 * row + 1] = __expf(LRELU_A * hi);
        wmax[warp] = hi;
    }
    __syncthreads();
    if (threadIdx.x == 0) {
        float m = wmax[0];
#pragma unroll
        for (int q = 1; q < 8; q++) m = fmaxf(m, wmax[q]);
        atomicMax(tmax, enc_f(m));
    }
}

// =================================================================
// Fused GAT attention (partial): fp16 mma.sync + cp.async + ldmatrix.
// BM rows x NFB cols per CTA, NTH threads, TPI 64-j subtiles/iter,
// SPLITJ-way j-split, CH row-chunks per warp (B-fragment reuse).
// E12 staged through cp.async into smem (sw128 layout) to kill the
// per-iteration L2 dependent-load chain. Writes RAW partials.
// =================================================================
template <int NF, int NFB, int BM, int NTH, int TPI, int SPLITJ, int CH, int MINB>
__global__ __launch_bounds__(NTH, MINB) void attn_mma(
    const __half* __restrict__ hTg, const uint32_t* __restrict__ bits,
    const float* __restrict__ sG, const float* __restrict__ abG,
    const int* __restrict__ tmaxI, const float* __restrict__ E12g,
    float* __restrict__ paccG, float* __restrict__ plG)
{
    constexpr int NW = NTH / 32;
    constexpr int WRB = BM / (16 * CH);         // row-group warps
    constexpr int WC = NW / WRB;                // col-group warps
    constexpr int PERCOL = NFB / WC;
    constexpr int NCT = PERCOL / 8;
    constexpr int NQ = NCT / 2;
    constexpr int THT = NFB * 128;
    constexpr int TPS = BM * 128;
    constexpr int HTB = TPI * THT;
    constexpr int PSB = TPI * TPS;
    constexpr int ESZ = TPI * 512;
    constexpr int EOFF = 2 * HTB + 2 * PSB;
    constexpr int PERT = NFB * 8 / NTH;
    constexpr int NIT = NN / (64 * TPI * SPLITJ);
    constexpr int NBLK = NF / NFB;
    constexpr int ROWDIV = NBLK * SPLITJ;
    constexpr int TPR = NTH / BM;               // phase-A threads per row
    constexpr int JPT = 64 / TPR;               // j per thread per subtile
    constexpr int NST = (JPT * 2) / 16;         // uint4 Ps stores per subtile
    constexpr int CB = JPT * 8;                 // E12 bytes per thread chunk

    extern __shared__ char smem[];
    const uint32_t sb = (uint32_t)__cvta_generic_to_shared(smem);

    const int tid = threadIdx.x;
    const int lane = tid & 31, w = tid >> 5;
    const int g = lane >> 2, tig = lane & 3;
    const int wr = w / WC, wc = w % WC;
    const int C0 = wc * PERCOL;
    const int bid = blockIdx.x;
    const int rb = bid / ROWDIV;
    const int r2 = bid % ROWDIV;
    const int cb = r2 / SPLITJ;
    const int jh = r2 % SPLITJ;
    const int i0 = rb * BM, c0 = cb * NFB;
    const int jbase = jh * (NN / SPLITJ);

    // phase-A mapping
    const int ar = tid / TPR, acg = tid % TPR;
    const float svp = sG[i0 + ar] + abG[0];
    const float Ma = svp + dec_f(tmaxI[0]);
    const float M = fmaxf(Ma, LRELU_A * Ma);
    const float c1 = __expf(svp - M);
    const float c2 = __expf(LRELU_A * svp - M);
    const float c3 = __expf(-svp);
    float lacc = 0.f;

    float acc[CH][NCT][4];
#pragma unroll
    for (int c = 0; c < CH; c++)
#pragma unroll
        for (int ct = 0; ct < NCT; ct++)
#pragma unroll
            for (int q = 0; q < 4; q++) acc[c][ct][q] = 0.f;

    const uint32_t* brow = bits + (size_t)(i0 + ar) * (NN / 32);
    const int bsh = (acg * JPT) & 31;
    const uint32_t xr = (uint32_t)((ar & 7) << 4);
    const uint32_t exr = (uint32_t)((((acg * JPT) >> 4) & 7) << 4);
    const uint32_t xO = (uint32_t)((lane & 7) << 4);
    const uint32_t aBoff = (uint32_t)((lane >> 4) << 4);
    const int bColB = (lane & 7) + ((lane >> 4) << 3);
    const uint32_t bBoff = (uint32_t)(((lane >> 3) & 1) << 4);

    uint32_t aOffA[4], bOffA[4];
#pragma unroll
    for (int k = 0; k < 4; k++) {
        aOffA[k] = (((uint32_t)(32 * k)) + aBoff) ^ xO;
        bOffA[k] = (((uint32_t)(32 * k)) + bBoff) ^ xO;
    }
    const uint32_t cBase = (uint32_t)(C0 + bColB) * 128;
    uint32_t aRowB[CH];
#pragma unroll
    for (int c = 0; c < CH; c++)
        aRowB[c] = (uint32_t)(wr * 16 + c * (WRB * 16) + (lane & 7) +
                              ((lane >> 3) & 1) * 8) * 128;

    uint32_t bwv[TPI];

#define ISSUE_CP(J0, BUF) do {                                                 \
    uint32_t hb = sb + (BUF) * HTB;                                            \
    _Pragma("unroll")                                                          \
    for (int tp = 0; tp < TPI; tp++) {                                         \
        _Pragma("unroll")                                                      \
        for (int u = 0; u < PERT; u++) {                                       \
            int ci = tid * PERT + u;                                           \
            int rr = ci >> 3, ch2 = ci & 7;                                    \
            uint32_t dst = hb + tp * THT + rr * 128 +                          \
                           (((uint32_t)(ch2 * 16)) ^ (((uint32_t)(rr & 7)) << 4)); \
            cp16(dst, hTg + (size_t)(c0 + rr) * NN + (J0) + tp * 64 + ch2 * 8); \
        }                                                                      \
    }                                                                          \
    if (tid < 32 * TPI) {                                                      \
        int tp2 = tid >> 5, f = tid & 31;                                      \
        uint32_t off = (uint32_t)(f * 16);                                     \
        uint32_t dst = sb + EOFF + (BUF) * ESZ + tp2 * 512 +                   \
                       (off ^ ((off >> 3) & 0x70u));                           \
        cp16(dst, E12g + 2 * ((J0) + tp2 * 64) + f * 4);                       \
    }                                                                          \
    asm volatile("cp.async.commit_group;" ::: "memory");                       \
} while (0)

#define LOAD_BITS(J0) do {                                                     \
    _Pragma("unroll")                                                          \
    for (int tp = 0; tp < TPI; tp++)                                           \
        bwv[tp] = brow[(((J0) + tp * 64) >> 5) + ((acg * JPT) >> 5)];          \
} while (0)

#define PHASE_A(BUF) do {                                                      \
    _Pragma("unroll")                                                          \
    for (int tp = 0; tp < TPI; tp++) {                                         \
        uint32_t mb = bwv[tp] >> bsh;                                          \
        const char* eb = smem + EOFF + (BUF) * ESZ + tp * 512 + acg * CB;      \
        union { __half2 h2[JPT / 2]; uint4 u[NST]; } cvv;                      \
        _Pragma("unroll")                                                      \
        for (int q = 0; q < JPT / 2; q++) {                                    \
            float4 v = *(const float4*)(eb + (((uint32_t)(q * 16)) ^ exr));    \
            float p0 = (v.x >= c3) ? c1 * v.x : c2 * v.y;                      \
            p0 = ((mb >> (2 * q)) & 1u) ? p0 : 0.f;                            \
            float p1 = (v.z >= c3) ? c1 * v.z : c2 * v.w;                      \
            p1 = ((mb >> (2 * q + 1)) & 1u) ? p1 : 0.f;                        \
            lacc += p0 + p1;                                                   \
            cvv.h2[q] = __floats2half2_rn(p0, p1);                             \
        }                                                                      \
        char* pbase = smem + 2 * HTB + (BUF) * PSB + tp * TPS + ar * 128;      \
        _Pragma("unroll")                                                      \
        for (int w2 = 0; w2 < NST; w2++)                                       \
            *(uint4*)(pbase + (((uint32_t)(acg * (JPT * 2) + w2 * 16)) ^ xr)) = cvv.u[w2]; \
    }                                                                          \
} while (0)

    // ---- prologue ----
    ISSUE_CP(jbase, 0);
    LOAD_BITS(jbase);
    asm volatile("cp.async.wait_group 0;" ::: "memory");
    __syncthreads();
    PHASE_A(0);

    for (int i = 0; i < NIT; i++) {
        const int cbf = i & 1, nb = (i + 1) & 1;
        const int jn = jbase + (i + 1) * 64 * TPI;
        if (i + 1 < NIT) {
            ISSUE_CP(jn, nb);
            LOAD_BITS(jn);
        }
        __syncthreads();      // Ps(i) visible; prev mma done reading buffers

        // ---- mma(i): B fragments shared across CH row-chunks ----
        const uint32_t psA0 = sb + 2 * HTB + (uint32_t)cbf * PSB;
        const uint32_t htA0 = sb + (uint32_t)cbf * HTB + cBase;
#pragma unroll
        for (int tp = 0; tp < TPI; tp++) {
            const uint32_t psA = psA0 + tp * TPS;
            const uint32_t htA = htA0 + tp * THT;
#pragma unroll
            for (int k = 0; k < 4; k++) {
                uint32_t A[CH][4];
#pragma unroll
                for (int c = 0; c < CH; c++)
                    ldsm4(A[c][0], A[c][1], A[c][2], A[c][3],
                          psA + aRowB[c] + aOffA[k]);
#pragma unroll
                for (int q = 0; q < NQ; q++) {
                    uint32_t b0, b1, b2, b3;
                    ldsm4(b0, b1, b2, b3, htA + (uint32_t)(q * 2048) + bOffA[k]);
#pragma unroll
                    for (int c = 0; c < CH; c++) {
                        mma16816(acc[c][2 * q + 0], A[c][0], A[c][1], A[c][2],
                                 A[c][3], b0, b1);
                        mma16816(acc[c][2 * q + 1], A[c][0], A[c][1], A[c][2],
                                 A[c][3], b2, b3);
                    }
                }
            }
        }

        if (i + 1 < NIT) {
            asm volatile("cp.async.wait_group 0;" ::: "memory");
            __syncthreads();  // Ht(i+1)/E12(i+1) landed; mma(i) done block-wide
            PHASE_A(nb);
        }
    }

    // ---- partial l (once per row; cb==0 only) ----
#pragma unroll
    for (int o = 1; o < TPR; o <<= 1)
        lacc += __shfl_xor_sync(0xffffffffu, lacc, o);
    if (acg == 0 && cb == 0) plG[jh * NN + i0 + ar] = lacc;

    // ---- raw partial acc ----
    float* pj = paccG + (size_t)jh * NN * NF;
#pragma unroll
    for (int c = 0; c < CH; c++) {
        const int r0 = i0 + wr * 16 + c * (WRB * 16) + g;
        const int r1 = r0 + 8;
#pragma unroll
        for (int ct = 0; ct < NCT; ct++) {
            int cc = c0 + C0 + 8 * ct + 2 * tig;
            *(float2*)(pj + (size_t)r0 * NF + cc) =
                make_float2(acc[c][ct][0], acc[c][ct][1]);
            *(float2*)(pj + (size_t)r1 * NF + cc) =
                make_float2(acc[c][ct][2], acc[c][ct][3]);
        }
    }
#undef ISSUE_CP
#undef LOAD_BITS
#undef PHASE_A
}

// =================================================================
// combine (mid layer): y = elu(elu((p0+p1)/(l0+l1))), elementwise
// =================================================================
__global__ __launch_bounds__(256) void comb_mid(
    const float* __restrict__ pacc, const float* __restrict__ pl,
    float* __restrict__ y)
{
    int idx = blockIdx.x * 256 + threadIdx.x;       // float4 index
    int row = idx / (FH / 4);
    float inv = 1.f / (pl[row] + pl[NN + row]);
    float4 a = ((const float4*)pacc)[idx];
    float4 b = ((const float4*)pacc)[idx + NN * (FH / 4)];
    float4 o;
    o.x = elu1(elu1((a.x + b.x) * inv));
    o.y = elu1(elu1((a.y + b.y) * inv));
    o.z = elu1(elu1((a.z + b.z) * inv));
    o.w = elu1(elu1((a.w + b.w) * inv));
    ((float4*)y)[idx] = o;
}

// =================================================================
// combine (final): out = log_softmax(elu((p0+p1)/(l0+l1))), per row
// =================================================================
__global__ __launch_bounds__(256) void comb_fin(
    const float* __restrict__ pacc, const float* __restrict__ pl,
    float* __restrict__ out)
{
    int tid = threadIdx.x;
    int qr = tid >> 3, ql = tid & 7;
    int row = blockIdx.x * 32 + qr;
    float inv = 1.f / (pl[row] + pl[NN + row]);
    const float* a0 = pacc + (size_t)row * FOUT + ql * 8;
    const float* a1 = a0 + (size_t)NN * FOUT;
    float z[8];
    {
        float4 u0 = ((const float4*)a0)[0], u1 = ((const float4*)a0)[1];
        float4 v0 = ((const float4*)a1)[0], v1 = ((const float4*)a1)[1];
        z[0] = elu1((u0.x + v0.x) * inv); z[1] = elu1((u0.y + v0.y) * inv);
        z[2] = elu1((u0.z + v0.z) * inv); z[3] = elu1((u0.w + v0.w) * inv);
        z[4] = elu1((u1.x + v1.x) * inv); z[5] = elu1((u1.y + v1.y) * inv);
        z[6] = elu1((u1.z + v1.z) * inv); z[7] = elu1((u1.w + v1.w) * inv);
    }
    float mx = z[0];
#pragma unroll
    for (int i = 1; i < 8; i++) mx = fmaxf(mx, z[i]);
    mx = fmaxf(mx, __shfl_xor_sync(0xffffffffu, mx, 1));
    mx = fmaxf(mx, __shfl_xor_sync(0xffffffffu, mx, 2));
    mx = fmaxf(mx, __shfl_xor_sync(0xffffffffu, mx, 4));
    float se = 0.f;
#pragma unroll
    for (int i = 0; i < 8; i++) se += __expf(z[i] - mx);
    se += __shfl_xor_sync(0xffffffffu, se, 1);
    se += __shfl_xor_sync(0xffffffffu, se, 2);
    se += __shfl_xor_sync(0xffffffffu, se, 4);
    float lse = mx + logf(se);
    float4 o0 = make_float4(z[0] - lse, z[1] - lse, z[2] - lse, z[3] - lse);
    float4 o1 = make_float4(z[4] - lse, z[5] - lse, z[6] - lse, z[7] - lse);
    float* op = out + (size_t)row * FOUT + ql * 8;
    ((float4*)op)[0] = o0;
    ((float4*)op)[1] = o1;
}

// =================================================================
extern "C" void kernel_launch(void* const* d_in, const int* in_sizes, int n_in,
                              void* d_out, int out_size)
{
    const float* x   = (const float*)d_in[0];
    const int*   adj = (const int*)  d_in[1];
    const float* W1  = (const float*)d_in[2];
    const float* b1  = (const float*)d_in[3];
    const float* a1  = (const float*)d_in[4];
    const float* ab1 = (const float*)d_in[5];
    const float* W2  = (const float*)d_in[6];
    const float* b2  = (const float*)d_in[7];
    const float* a2  = (const float*)d_in[8];
    const float* ab2 = (const float*)d_in[9];
    float* out = (float*)d_out;

    void *h1p, *y1p, *h2p, *h1tp, *h2tp, *s1p, *t1p, *s2p, *t2p, *tmp, *abp,
         *e12p, *pap, *plp;
    cudaGetSymbolAddress(&h1p, g_h1);
    cudaGetSymbolAddress(&y1p, g_y1);
    cudaGetSymbolAddress(&h2p, g_h2);
    cudaGetSymbolAddress(&h1tp, g_h1T);
    cudaGetSymbolAddress(&h2tp, g_h2T);
    cudaGetSymbolAddress(&s1p, g_s1);
    cudaGetSymbolAddress(&t1p, g_t1);
    cudaGetSymbolAddress(&s2p, g_s2);
    cudaGetSymbolAddress(&t2p, g_t2);
    cudaGetSymbolAddress(&tmp, g_tmaxi);
    cudaGetSymbolAddress(&abp, g_adjbits);
    cudaGetSymbolAddress(&e12p, g_E12);
    cudaGetSymbolAddress(&pap, g_pacc);
    cudaGetSymbolAddress(&plp, g_pl);
    float* h1 = (float*)h1p; float* y1 = (float*)y1p; float* h2 = (float*)h2p;
    __half* h1T = (__half*)h1tp; __half* h2T = (__half*)h2tp;
    float* s1 = (float*)s1p; float* t1 = (float*)t1p;
    float* s2 = (float*)s2p; float* t2 = (float*)t2p;
    int* tmaxi = (int*)tmp;
    uint32_t* abits = (uint32_t*)abp;
    float* E12 = (float*)e12p;
    float* pacc = (float*)pap;
    float* pl = (float*)plp;

    // attn1: NFB=128, BM=64, 256thr, TPI=1, SPLITJ=2, CH=2, 3 CTAs/SM
    // attn2: NFB=64,  BM=16, 128thr, TPI=1, SPLITJ=2, CH=1, 8 CTAs/SM
    const int SM1 = 2 * (128 * 128) + 2 * (64 * 128) + 2 * 512;   // 50176
    const int SM2 = 2 * (64 * 128) + 2 * (16 * 128) + 2 * 512;    // 21504
    cudaFuncSetAttribute((const void*)attn_mma<FH, 128, 64, 256, 1, 2, 2, 3>,
                         cudaFuncAttributeMaxDynamicSharedMemorySize, SM1);
    cudaFuncSetAttribute((const void*)attn_mma<FOUT, 64, 16, 128, 1, 2, 1, 8>,
                         cudaFuncAttributeMaxDynamicSharedMemorySize, SM2);

    // Layer 1  (attn_mma is the 4th launch -> gets profiled by ncu)
    gemm_bias<<<dim3(FH / 64, NN / 128), 256>>>(x, W1, b1, h1, NN, FH, FIN);
    transpose_pack<<<dim3(NN / 32, FH / 32, 2), 256>>>(h1, h1T, FH, adj, abits);
    st_kernel<FH><<<NN / 8, 256>>>(h1, a1, s1, t1, E12, tmaxi);
    attn_mma<FH, 128, 64, 256, 1, 2, 2, 3><<<(NN / 64) * 4, 256, SM1>>>(
        h1T, abits, s1, ab1, tmaxi, E12, pacc, pl);
    comb_mid<<<NN * FH / 4 / 256, 256>>>(pacc, pl, y1);

    // Layer 2
    gemm_bias<<<dim3(FOUT / 64, NN / 128), 256>>>(y1, W2, b2, h2, NN, FOUT, FH);
    transpose_pack<<<dim3(NN / 32, FOUT / 32, 1), 256>>>(h2, h2T, FOUT, adj, abits);
    st_kernel<FOUT><<<NN / 8, 256>>>(h2, a2, s2, t2, E12, tmaxi + 1);
    attn_mma<FOUT, 64, 16, 128, 1, 2, 1, 8><<<(NN / 16) * 2, 128, SM2>>>(
        h2T, abits, s2, ab2, tmaxi + 1, E12, pacc, pl);
    comb_fin<<<NN / 32, 256>>>(pacc, pl, out);
}

// round 17
// speedup vs baseline: 1.5794x; 1.0648x over previous
#include <cuda_runtime.h>
#include <cuda_fp16.h>
#include <math.h>
#include <stdint.h>

#define NN 8192
#define FIN 512
#define FH 256
#define FOUT 64
#define LRELU_A 0.2f

// ---------------- scratch (no allocations allowed) ----------------
__device__ float g_h1[NN * FH];
__device__ float g_y1[NN * FH];
__device__ float g_h2[NN * FOUT];
__device__ __half g_h1T[FH * NN];
__device__ __half g_h2T[FOUT * NN];
__device__ float g_s1[NN], g_t1[NN];
__device__ float g_s2[NN], g_t2[NN];
__device__ int g_tmaxi[2];
__device__ uint32_t g_adjbits[(size_t)NN * (NN / 32)];
__device__ __align__(16) float g_E12[2 * NN];          // (exp(t), exp(0.2t)) per j
__device__ float g_pacc[2 * (size_t)NN * FH];          // split-j partial acc (reused)
__device__ float g_pl[4 * NN];                         // split-j partial l

__device__ __forceinline__ float elu1(float x) { return x > 0.f ? x : expm1f(x); }

__device__ __forceinline__ int enc_f(float f) {
    int i = __float_as_int(f);
    return i < 0 ? (i ^ 0x7fffffff) : i;
}
__device__ __forceinline__ float dec_f(int i) {
    return __int_as_float(i < 0 ? (i ^ 0x7fffffff) : i);
}

__device__ __forceinline__ void ldsm4(uint32_t& r0, uint32_t& r1, uint32_t& r2,
                                      uint32_t& r3, uint32_t addr) {
    asm volatile("ldmatrix.sync.aligned.m8n8.x4.shared.b16 {%0,%1,%2,%3}, [%4];"
                 : "=r"(r0), "=r"(r1), "=r"(r2), "=r"(r3) : "r"(addr));
}

__device__ __forceinline__ void mma16816(float d[4], uint32_t a0, uint32_t a1,
                                         uint32_t a2, uint32_t a3,
                                         uint32_t b0, uint32_t b1) {
    asm volatile(
        "mma.sync.aligned.m16n8k16.row.col.f32.f16.f16.f32 "
        "{%0,%1,%2,%3}, {%4,%5,%6,%7}, {%8,%9}, {%0,%1,%2,%3};"
        : "+f"(d[0]), "+f"(d[1]), "+f"(d[2]), "+f"(d[3])
        : "r"(a0), "r"(a1), "r"(a2), "r"(a3), "r"(b0), "r"(b1));
}

__device__ __forceinline__ void cp16(uint32_t dst, const void* src) {
    asm volatile("cp.async.cg.shared.global [%0], [%1], 16;" :: "r"(dst), "l"(src));
}

// =================================================================
// GEMM: C[M,N] = A[M,K] @ W[N,K]^T + bias[N]. Also re-inits tmax ints.
// =================================================================
__global__ __launch_bounds__(256) void gemm_bias(
    const float* __restrict__ A, const float* __restrict__ W,
    const float* __restrict__ bias, float* __restrict__ C,
    int M, int N, int K)
{
    const int BM = 128, BN = 64, BK = 16;
    __shared__ float As[BK][BM + 1];
    __shared__ float Bs[BK][BN + 1];

    int tid = threadIdx.x;
    int bx = blockIdx.x, by = blockIdx.y;
    if (bx == 0 && by == 0 && tid == 0) {
        g_tmaxi[0] = (int)0x80000000;
        g_tmaxi[1] = (int)0x80000000;
    }
    int ty = tid >> 4, tx = tid & 15;
    int ar = tid >> 2, ac4 = (tid & 3) * 4;

    float acc[8][4];
#pragma unroll
    for (int i = 0; i < 8; i++)
#pragma unroll
        for (int j = 0; j < 4; j++) acc[i][j] = 0.f;

    for (int k0 = 0; k0 < K; k0 += BK) {
        float4 a0 = *(const float4*)(A + (size_t)(by * BM + ar) * K + k0 + ac4);
        float4 a1 = *(const float4*)(A + (size_t)(by * BM + ar + 64) * K + k0 + ac4);
        float4 b0 = *(const float4*)(W + (size_t)(bx * BN + ar) * K + k0 + ac4);
        __syncthreads();
        As[ac4 + 0][ar] = a0.x; As[ac4 + 1][ar] = a0.y;
        As[ac4 + 2][ar] = a0.z; As[ac4 + 3][ar] = a0.w;
        As[ac4 + 0][ar + 64] = a1.x; As[ac4 + 1][ar + 64] = a1.y;
        As[ac4 + 2][ar + 64] = a1.z; As[ac4 + 3][ar + 64] = a1.w;
        Bs[ac4 + 0][ar] = b0.x; Bs[ac4 + 1][ar] = b0.y;
        Bs[ac4 + 2][ar] = b0.z; Bs[ac4 + 3][ar] = b0.w;
        __syncthreads();
#pragma unroll
        for (int k = 0; k < BK; k++) {
            float ra[8], rb[4];
#pragma unroll
            for (int i = 0; i < 8; i++) ra[i] = As[k][ty * 8 + i];
#pragma unroll
            for (int j = 0; j < 4; j++) rb[j] = Bs[k][tx * 4 + j];
#pragma unroll
            for (int i = 0; i < 8; i++)
#pragma unroll
                for (int j = 0; j < 4; j++) acc[i][j] = fmaf(ra[i], rb[j], acc[i][j]);
        }
    }

    float4 bv = ((const float4*)bias)[bx * 16 + tx];
#pragma unroll
    for (int i = 0; i < 8; i++) {
        int row = by * BM + ty * 8 + i;
        float4 v;
        v.x = acc[i][0] + bv.x; v.y = acc[i][1] + bv.y;
        v.z = acc[i][2] + bv.z; v.w = acc[i][3] + bv.w;
        ((float4*)(C + (size_t)row * N))[bx * 16 + tx] = v;
    }
}

// =================================================================
// transpose + fp16 convert (z==0); adjacency bit-pack (z==1)
// =================================================================
__global__ __launch_bounds__(256) void transpose_pack(
    const float* __restrict__ h, __half* __restrict__ hT, int F,
    const int* __restrict__ adj, uint32_t* __restrict__ bits)
{
    if (blockIdx.z == 1) {
        int bid = blockIdx.x + blockIdx.y * gridDim.x;
        int wd = threadIdx.x;
#pragma unroll
        for (int r = 0; r < 4; r++) {
            int row = bid * 4 + r;
            const int4* src = (const int4*)(adj + (size_t)row * NN + wd * 32);
            uint32_t m = 0;
#pragma unroll
            for (int q = 0; q < 8; q++) {
                int4 v = src[q];
                m |= (v.x != 0 ? 1u : 0u) << (q * 4 + 0);
                m |= (v.y != 0 ? 1u : 0u) << (q * 4 + 1);
                m |= (v.z != 0 ? 1u : 0u) << (q * 4 + 2);
                m |= (v.w != 0 ? 1u : 0u) << (q * 4 + 3);
            }
            bits[(size_t)row * (NN / 32) + wd] = m;
        }
        return;
    }

    __shared__ float ts[32][33];
    int n0 = blockIdx.x * 32, c0 = blockIdx.y * 32;
    int r = threadIdx.x >> 3, cc = (threadIdx.x & 7) * 4;

    float4 v = *(const float4*)(h + (size_t)(n0 + r) * F + c0 + cc);
    ts[r][cc + 0] = v.x; ts[r][cc + 1] = v.y;
    ts[r][cc + 2] = v.z; ts[r][cc + 3] = v.w;
    __syncthreads();

    int c = threadIdx.x >> 3, nn2 = (threadIdx.x & 7) * 4;
    __half2 p0 = __floats2half2_rn(ts[nn2 + 0][c], ts[nn2 + 1][c]);
    __half2 p1 = __floats2half2_rn(ts[nn2 + 2][c], ts[nn2 + 3][c]);
    union { __half2 h2[2]; uint2 u; } cv;
    cv.h2[0] = p0; cv.h2[1] = p1;
    *(uint2*)(hT + (size_t)(c0 + c) * NN + n0 + nn2) = cv.u;
}

// =================================================================
// s/t projections + E12 table + block-reduced atomicMax of t
// =================================================================
template <int F>
__global__ __launch_bounds__(256) void st_kernel(
    const float* __restrict__ h, const float* __restrict__ a,
    float* __restrict__ s, float* __restrict__ t,
    float* __restrict__ E12, int* __restrict__ tmax)
{
    __shared__ float wmax[8];
    int warp = threadIdx.x >> 5, lane = threadIdx.x & 31;
    int row = blockIdx.x * 8 + warp;
    const float* hr = h + (size_t)row * F;
    float lo = 0.f, hi = 0.f;
#pragma unroll
    for (int f = lane; f < F; f += 32) {
        float v = hr[f];
        lo = fmaf(v, a[f], lo);
        hi = fmaf(v, a[F + f], hi);
    }
#pragma unroll
    for (int o = 16; o; o >>= 1) {
        lo += __shfl_xor_sync(0xffffffffu, lo, o);
        hi += __shfl_xor_sync(0xffffffffu, hi, o);
    }
    if (lane == 0) {
        s[row] = lo; t[row] = hi;
        E12[2 * row] = __expf(hi);
        E12[2 * row + 1] = __expf(LRELU_A * hi);
        wmax[warp] = hi;
    }
    __syncthreads();
    if (threadIdx.x == 0) {
        float m = wmax[0];
#pragma unroll
        for (int q = 1; q < 8; q++) m = fmaxf(m, wmax[q]);
        atomicMax(tmax, enc_f(m));
    }
}

// =================================================================
// Fused GAT attention (partial): fp16 mma.sync + cp.async + ldmatrix.
// BM rows x NFB cols per CTA, NTH threads, TPI 64-j subtiles/iter,
// SPLITJ-way j-split, CH row-chunks per warp (B-fragment reuse).
// E12 staged through cp.async into smem (sw128 layout). Raw partials.
// =================================================================
template <int NF, int NFB, int BM, int NTH, int TPI, int SPLITJ, int CH, int MINB>
__global__ __launch_bounds__(NTH, MINB) void attn_mma(
    const __half* __restrict__ hTg, const uint32_t* __restrict__ bits,
    const float* __restrict__ sG, const float* __restrict__ abG,
    const int* __restrict__ tmaxI, const float* __restrict__ E12g,
    float* __restrict__ paccG, float* __restrict__ plG)
{
    constexpr int NW = NTH / 32;
    constexpr int WRB = BM / (16 * CH);         // row-group warps
    constexpr int WC = NW / WRB;                // col-group warps
    constexpr int PERCOL = NFB / WC;
    constexpr int NCT = PERCOL / 8;
    constexpr int NQ = NCT / 2;
    constexpr int THT = NFB * 128;
    constexpr int TPS = BM * 128;
    constexpr int HTB = TPI * THT;
    constexpr int PSB = TPI * TPS;
    constexpr int ESZ = TPI * 512;
    constexpr int EOFF = 2 * HTB + 2 * PSB;
    constexpr int PERT = NFB * 8 / NTH;
    constexpr int NIT = NN / (64 * TPI * SPLITJ);
    constexpr int NBLK = NF / NFB;
    constexpr int ROWDIV = NBLK * SPLITJ;
    constexpr int TPR = NTH / BM;               // phase-A threads per row
    constexpr int JPT = 64 / TPR;               // j per thread per subtile
    constexpr int NST = (JPT * 2) / 16;         // uint4 Ps stores per subtile
    constexpr int CB = JPT * 8;                 // E12 bytes per thread chunk

    extern __shared__ char smem[];
    const uint32_t sb = (uint32_t)__cvta_generic_to_shared(smem);

    const int tid = threadIdx.x;
    const int lane = tid & 31, w = tid >> 5;
    const int g = lane >> 2, tig = lane & 3;
    const int wr = w / WC, wc = w % WC;
    const int C0 = wc * PERCOL;
    const int bid = blockIdx.x;
    const int rb = bid / ROWDIV;
    const int r2 = bid % ROWDIV;
    const int cb = r2 / SPLITJ;
    const int jh = r2 % SPLITJ;
    const int i0 = rb * BM, c0 = cb * NFB;
    const int jbase = jh * (NN / SPLITJ);

    // phase-A mapping
    const int ar = tid / TPR, acg = tid % TPR;
    const float svp = sG[i0 + ar] + abG[0];
    const float Ma = svp + dec_f(tmaxI[0]);
    const float M = fmaxf(Ma, LRELU_A * Ma);
    const float c1 = __expf(svp - M);
    const float c2 = __expf(LRELU_A * svp - M);
    const float c3 = __expf(-svp);
    float lacc = 0.f;

    float acc[CH][NCT][4];
#pragma unroll
    for (int c = 0; c < CH; c++)
#pragma unroll
        for (int ct = 0; ct < NCT; ct++)
#pragma unroll
            for (int q = 0; q < 4; q++) acc[c][ct][q] = 0.f;

    const uint32_t* brow = bits + (size_t)(i0 + ar) * (NN / 32);
    const int bsh = (acg * JPT) & 31;
    const uint32_t xr = (uint32_t)((ar & 7) << 4);
    const uint32_t exr = (uint32_t)((((acg * JPT) >> 4) & 7) << 4);
    const uint32_t xO = (uint32_t)((lane & 7) << 4);
    const uint32_t aBoff = (uint32_t)((lane >> 4) << 4);
    const int bColB = (lane & 7) + ((lane >> 4) << 3);
    const uint32_t bBoff = (uint32_t)(((lane >> 3) & 1) << 4);

    uint32_t aOffA[4], bOffA[4];
#pragma unroll
    for (int k = 0; k < 4; k++) {
        aOffA[k] = (((uint32_t)(32 * k)) + aBoff) ^ xO;
        bOffA[k] = (((uint32_t)(32 * k)) + bBoff) ^ xO;
    }
    const uint32_t cBase = (uint32_t)(C0 + bColB) * 128;
    uint32_t aRowB[CH];
#pragma unroll
    for (int c = 0; c < CH; c++)
        aRowB[c] = (uint32_t)(wr * 16 + c * (WRB * 16) + (lane & 7) +
                              ((lane >> 3) & 1) * 8) * 128;

    uint32_t bwv[TPI];

#define ISSUE_CP(J0, BUF) do {                                                 \
    uint32_t hb = sb + (BUF) * HTB;                                            \
    _Pragma("unroll")                                                          \
    for (int tp = 0; tp < TPI; tp++) {                                         \
        _Pragma("unroll")                                                      \
        for (int u = 0; u < PERT; u++) {                                       \
            int ci = tid * PERT + u;                                           \
            int rr = ci >> 3, ch2 = ci & 7;                                    \
            uint32_t dst = hb + tp * THT + rr * 128 +                          \
                           (((uint32_t)(ch2 * 16)) ^ (((uint32_t)(rr & 7)) << 4)); \
            cp16(dst, hTg + (size_t)(c0 + rr) * NN + (J0) + tp * 64 + ch2 * 8); \
        }                                                                      \
    }                                                                          \
    if (tid < 32 * TPI) {                                                      \
        int tp2 = tid >> 5, f = tid & 31;                                      \
        uint32_t off = (uint32_t)(f * 16);                                     \
        uint32_t dst = sb + EOFF + (BUF) * ESZ + tp2 * 512 +                   \
                       (off ^ ((off >> 3) & 0x70u));                           \
        cp16(dst, E12g + 2 * ((J0) + tp2 * 64) + f * 4);                       \
    }                                                                          \
    asm volatile("cp.async.commit_group;" ::: "memory");                       \
} while (0)

#define LOAD_BITS(J0) do {                                                     \
    _Pragma("unroll")                                                          \
    for (int tp = 0; tp < TPI; tp++)                                           \
        bwv[tp] = brow[(((J0) + tp * 64) >> 5) + ((acg * JPT) >> 5)];          \
} while (0)

#define PHASE_A(BUF) do {                                                      \
    _Pragma("unroll")                                                          \
    for (int tp = 0; tp < TPI; tp++) {                                         \
        uint32_t mb = bwv[tp] >> bsh;                                          \
        const char* eb = smem + EOFF + (BUF) * ESZ + tp * 512 + acg * CB;      \
        union { __half2 h2[JPT / 2]; uint4 u[NST]; } cvv;                      \
        _Pragma("unroll")                                                      \
        for (int q = 0; q < JPT / 2; q++) {                                    \
            float4 v = *(const float4*)(eb + (((uint32_t)(q * 16)) ^ exr));    \
            float p0 = (v.x >= c3) ? c1 * v.x : c2 * v.y;                      \
            p0 = ((mb >> (2 * q)) & 1u) ? p0 : 0.f;                            \
            float p1 = (v.z >= c3) ? c1 * v.z : c2 * v.w;                      \
            p1 = ((mb >> (2 * q + 1)) & 1u) ? p1 : 0.f;                        \
            lacc += p0 + p1;                                                   \
            cvv.h2[q] = __floats2half2_rn(p0, p1);                             \
        }                                                                      \
        char* pbase = smem + 2 * HTB + (BUF) * PSB + tp * TPS + ar * 128;      \
        _Pragma("unroll")                                                      \
        for (int w2 = 0; w2 < NST; w2++)                                       \
            *(uint4*)(pbase + (((uint32_t)(acg * (JPT * 2) + w2 * 16)) ^ xr)) = cvv.u[w2]; \
    }                                                                          \
} while (0)

    // ---- prologue ----
    ISSUE_CP(jbase, 0);
    LOAD_BITS(jbase);
    asm volatile("cp.async.wait_group 0;" ::: "memory");
    __syncthreads();
    PHASE_A(0);

    for (int i = 0; i < NIT; i++) {
        const int cbf = i & 1, nb = (i + 1) & 1;
        const int jn = jbase + (i + 1) * 64 * TPI;
        if (i + 1 < NIT) {
            ISSUE_CP(jn, nb);
            LOAD_BITS(jn);
        }
        __syncthreads();      // Ps(i) visible; prev mma done reading buffers

        // ---- mma(i): B fragments shared across CH row-chunks ----
        const uint32_t psA0 = sb + 2 * HTB + (uint32_t)cbf * PSB;
        const uint32_t htA0 = sb + (uint32_t)cbf * HTB + cBase;
#pragma unroll
        for (int tp = 0; tp < TPI; tp++) {
            const uint32_t psA = psA0 + tp * TPS;
            const uint32_t htA = htA0 + tp * THT;
#pragma unroll
            for (int k = 0; k < 4; k++) {
                uint32_t A[CH][4];
#pragma unroll
                for (int c = 0; c < CH; c++)
                    ldsm4(A[c][0], A[c][1], A[c][2], A[c][3],
                          psA + aRowB[c] + aOffA[k]);
#pragma unroll
                for (int q = 0; q < NQ; q++) {
                    uint32_t b0, b1, b2, b3;
                    ldsm4(b0, b1, b2, b3, htA + (uint32_t)(q * 2048) + bOffA[k]);
#pragma unroll
                    for (int c = 0; c < CH; c++) {
                        mma16816(acc[c][2 * q + 0], A[c][0], A[c][1], A[c][2],
                                 A[c][3], b0, b1);
                        mma16816(acc[c][2 * q + 1], A[c][0], A[c][1], A[c][2],
                                 A[c][3], b2, b3);
                    }
                }
            }
        }

        if (i + 1 < NIT) {
            asm volatile("cp.async.wait_group 0;" ::: "memory");
            __syncthreads();  // Ht(i+1)/E12(i+1) landed; mma(i) done block-wide
            PHASE_A(nb);
        }
    }

    // ---- partial l (once per row; cb==0 only) ----
#pragma unroll
    for (int o = 1; o < TPR; o <<= 1)
        lacc += __shfl_xor_sync(0xffffffffu, lacc, o);
    if (acg == 0 && cb == 0) plG[jh * NN + i0 + ar] = lacc;

    // ---- raw partial acc ----
    float* pj = paccG + (size_t)jh * NN * NF;
#pragma unroll
    for (int c = 0; c < CH; c++) {
        const int r0 = i0 + wr * 16 + c * (WRB * 16) + g;
        const int r1 = r0 + 8;
#pragma unroll
        for (int ct = 0; ct < NCT; ct++) {
            int cc = c0 + C0 + 8 * ct + 2 * tig;
            *(float2*)(pj + (size_t)r0 * NF + cc) =
                make_float2(acc[c][ct][0], acc[c][ct][1]);
            *(float2*)(pj + (size_t)r1 * NF + cc) =
                make_float2(acc[c][ct][2], acc[c][ct][3]);
        }
    }
#undef ISSUE_CP
#undef LOAD_BITS
#undef PHASE_A
}

// =================================================================
// combine (mid layer): y = elu(elu((p0+p1)/(l0+l1))), elementwise
// =================================================================
__global__ __launch_bounds__(256) void comb_mid(
    const float* __restrict__ pacc, const float* __restrict__ pl,
    float* __restrict__ y)
{
    int idx = blockIdx.x * 256 + threadIdx.x;       // float4 index
    int row = idx / (FH / 4);
    float inv = 1.f / (pl[row] + pl[NN + row]);
    float4 a = ((const float4*)pacc)[idx];
    float4 b = ((const float4*)pacc)[idx + NN * (FH / 4)];
    float4 o;
    o.x = elu1(elu1((a.x + b.x) * inv));
    o.y = elu1(elu1((a.y + b.y) * inv));
    o.z = elu1(elu1((a.z + b.z) * inv));
    o.w = elu1(elu1((a.w + b.w) * inv));
    ((float4*)y)[idx] = o;
}

// =================================================================
// combine (final, 4-way split): out = log_softmax(elu(sum(p)/sum(l)))
// =================================================================
__global__ __launch_bounds__(256) void comb_fin(
    const float* __restrict__ pacc, const float* __restrict__ pl,
    float* __restrict__ out)
{
    int tid = threadIdx.x;
    int qr = tid >> 3, ql = tid & 7;
    int row = blockIdx.x * 32 + qr;
    float inv = 1.f / (pl[row] + pl[NN + row] + pl[2 * NN + row] + pl[3 * NN + row]);
    float z[8];
#pragma unroll
    for (int q = 0; q < 2; q++) {
        float4 s = make_float4(0.f, 0.f, 0.f, 0.f);
#pragma unroll
        for (int jh = 0; jh < 4; jh++) {
            const float* ap = pacc + (size_t)jh * NN * FOUT + (size_t)row * FOUT + ql * 8;
            float4 v = ((const float4*)ap)[q];
            s.x += v.x; s.y += v.y; s.z += v.z; s.w += v.w;
        }
        z[4 * q + 0] = elu1(s.x * inv); z[4 * q + 1] = elu1(s.y * inv);
        z[4 * q + 2] = elu1(s.z * inv); z[4 * q + 3] = elu1(s.w * inv);
    }
    float mx = z[0];
#pragma unroll
    for (int i = 1; i < 8; i++) mx = fmaxf(mx, z[i]);
    mx = fmaxf(mx, __shfl_xor_sync(0xffffffffu, mx, 1));
    mx = fmaxf(mx, __shfl_xor_sync(0xffffffffu, mx, 2));
    mx = fmaxf(mx, __shfl_xor_sync(0xffffffffu, mx, 4));
    float se = 0.f;
#pragma unroll
    for (int i = 0; i < 8; i++) se += __expf(z[i] - mx);
    se += __shfl_xor_sync(0xffffffffu, se, 1);
    se += __shfl_xor_sync(0xffffffffu, se, 2);
    se += __shfl_xor_sync(0xffffffffu, se, 4);
    float lse = mx + logf(se);
    float4 o0 = make_float4(z[0] - lse, z[1] - lse, z[2] - lse, z[3] - lse);
    float4 o1 = make_float4(z[4] - lse, z[5] - lse, z[6] - lse, z[7] - lse);
    float* op = out + (size_t)row * FOUT + ql * 8;
    ((float4*)op)[0] = o0;
    ((float4*)op)[1] = o1;
}

// =================================================================
extern "C" void kernel_launch(void* const* d_in, const int* in_sizes, int n_in,
                              void* d_out, int out_size)
{
    const float* x   = (const float*)d_in[0];
    const int*   adj = (const int*)  d_in[1];
    const float* W1  = (const float*)d_in[2];
    const float* b1  = (const float*)d_in[3];
    const float* a1  = (const float*)d_in[4];
    const float* ab1 = (const float*)d_in[5];
    const float* W2  = (const float*)d_in[6];
    const float* b2  = (const float*)d_in[7];
    const float* a2  = (const float*)d_in[8];
    const float* ab2 = (const float*)d_in[9];
    float* out = (float*)d_out;

    void *h1p, *y1p, *h2p, *h1tp, *h2tp, *s1p, *t1p, *s2p, *t2p, *tmp, *abp,
         *e12p, *pap, *plp;
    cudaGetSymbolAddress(&h1p, g_h1);
    cudaGetSymbolAddress(&y1p, g_y1);
    cudaGetSymbolAddress(&h2p, g_h2);
    cudaGetSymbolAddress(&h1tp, g_h1T);
    cudaGetSymbolAddress(&h2tp, g_h2T);
    cudaGetSymbolAddress(&s1p, g_s1);
    cudaGetSymbolAddress(&t1p, g_t1);
    cudaGetSymbolAddress(&s2p, g_s2);
    cudaGetSymbolAddress(&t2p, g_t2);
    cudaGetSymbolAddress(&tmp, g_tmaxi);
    cudaGetSymbolAddress(&abp, g_adjbits);
    cudaGetSymbolAddress(&e12p, g_E12);
    cudaGetSymbolAddress(&pap, g_pacc);
    cudaGetSymbolAddress(&plp, g_pl);
    float* h1 = (float*)h1p; float* y1 = (float*)y1p; float* h2 = (float*)h2p;
    __half* h1T = (__half*)h1tp; __half* h2T = (__half*)h2tp;
    float* s1 = (float*)s1p; float* t1 = (float*)t1p;
    float* s2 = (float*)s2p; float* t2 = (float*)t2p;
    int* tmaxi = (int*)tmp;
    uint32_t* abits = (uint32_t*)abp;
    float* E12 = (float*)e12p;
    float* pacc = (float*)pap;
    float* pl = (float*)plp;

    // attn1: NFB=128, BM=64, 256thr, TPI=1, SPLITJ=2, CH=2, 3 CTAs/SM
    // attn2: NFB=64,  BM=64, 256thr, TPI=1, SPLITJ=4, CH=2, 4 CTAs/SM
    const int SM1 = 2 * (128 * 128) + 2 * (64 * 128) + 2 * 512;   // 50176
    const int SM2 = 2 * (64 * 128) + 2 * (64 * 128) + 2 * 512;    // 33792
    cudaFuncSetAttribute((const void*)attn_mma<FH, 128, 64, 256, 1, 2, 2, 3>,
                         cudaFuncAttributeMaxDynamicSharedMemorySize, SM1);
    cudaFuncSetAttribute((const void*)attn_mma<FOUT, 64, 64, 256, 1, 4, 2, 4>,
                         cudaFuncAttributeMaxDynamicSharedMemorySize, SM2);

    // Layer 1  (attn_mma is the 4th launch -> gets profiled by ncu)
    gemm_bias<<<dim3(FH / 64, NN / 128), 256>>>(x, W1, b1, h1, NN, FH, FIN);
    transpose_pack<<<dim3(NN / 32, FH / 32, 2), 256>>>(h1, h1T, FH, adj, abits);
    st_kernel<FH><<<NN / 8, 256>>>(h1, a1, s1, t1, E12, tmaxi);
    attn_mma<FH, 128, 64, 256, 1, 2, 2, 3><<<(NN / 64) * 4, 256, SM1>>>(
        h1T, abits, s1, ab1, tmaxi, E12, pacc, pl);
    comb_mid<<<NN * FH / 4 / 256, 256>>>(pacc, pl, y1);

    // Layer 2
    gemm_bias<<<dim3(FOUT / 64, NN / 128), 256>>>(y1, W2, b2, h2, NN, FOUT, FH);
    transpose_pack<<<dim3(NN / 32, FOUT / 32, 1), 256>>>(h2, h2T, FOUT, adj, abits);
    st_kernel<FOUT><<<NN / 8, 256>>>(h2, a2, s2, t2, E12, tmaxi + 1);
    attn_mma<FOUT, 64, 64, 256, 1, 4, 2, 4><<<(NN / 64) * 4, 256, SM2>>>(
        h2T, abits, s2, ab2, tmaxi + 1, E12, pacc, pl);
    comb_fin<<<NN / 32, 256>>>(pacc, pl, out);
}